// round 13
// baseline (speedup 1.0000x reference)
#include <cuda_runtime.h>
#include <cstdint>

// ---------------- problem constants ----------------
#define TOK    131072              // B*H*W tokens (raster order)
#define HSZ    25165824            // 8*192*128*128 (one output tensor)

// ---------------- static device scratch ----------------
__device__ float g_proj[(size_t)TOK * 192];   // in_proj out (raw, pre-LN)
__device__ float g_qkv [(size_t)TOK * 576];
__device__ float g_attn[(size_t)TOK * 192];
__device__ float g_amap[(size_t)TOK * 192];   // out_proj out (raw, pre-GN)
__device__ float g_hraw[(size_t)TOK * 192];   // BCHW layout
__device__ float g_wperm[768 * 192];          // permuted gates weight
__device__ float g_bperm[768];
__device__ float g_lns[TOK], g_lnq[TOK];      // LN sums (atomic)
__device__ float g_g1s[64], g_g1q[64];        // GN1 sums (atomic)
__device__ float g_g2s[64], g_g2q[64];        // GN2 sums (atomic)

// ---------------- PTX helpers ----------------
#define CP_ASYNC16(sm, gp) \
    asm volatile("cp.async.cg.shared.global [%0], [%1], 16;" :: "r"((uint32_t)(sm)), "l"(gp))
#define CP_COMMIT() asm volatile("cp.async.commit_group;" ::: "memory")
#define CP_WAIT(n)  asm volatile("cp.async.wait_group %0;" :: "n"(n) : "memory")

__device__ __forceinline__ uint32_t smem_to_u32(const void* p) {
    uint32_t a;
    asm("{ .reg .u64 t; cvta.to.shared.u64 t, %1; cvt.u32.u64 %0, t; }" : "=r"(a) : "l"(p));
    return a;
}
__device__ __forceinline__ void mma_tf32(float& c0, float& c1, float& c2, float& c3,
                                         uint32_t a0, uint32_t a1, uint32_t a2, uint32_t a3,
                                         uint32_t b0, uint32_t b1) {
    asm volatile("mma.sync.aligned.m16n8k8.row.col.f32.tf32.tf32.f32 "
                 "{%0,%1,%2,%3}, {%4,%5,%6,%7}, {%8,%9}, {%0,%1,%2,%3};"
                 : "+f"(c0), "+f"(c1), "+f"(c2), "+f"(c3)
                 : "r"(a0), "r"(a1), "r"(a2), "r"(a3), "r"(b0), "r"(b1));
}

// =====================================================================
// prep: permute gates weight/bias + zero atomic accumulators
// =====================================================================
__global__ __launch_bounds__(192)
void k_prep(const float* __restrict__ wg, const float* __restrict__ bg)
{
    int col = blockIdx.x;
    int t = col >> 6, l = col & 63;
    int half = l >> 5, l2 = l & 31, b = l2 >> 4, l3 = l2 & 15;
    int ghi = l3 >> 3, l4 = l3 & 7, q = l4 >> 1, glo = l4 & 1;
    int gate = ghi * 2 + glo;
    int ch = t * 16 + half * 8 + b * 4 + q;
    int orow = gate * 192 + ch;
    g_wperm[col * 192 + threadIdx.x] = wg[orow * 192 + threadIdx.x];
    if (threadIdx.x == 0) g_bperm[col] = bg[orow];

    int idx = blockIdx.x * 192 + threadIdx.x;
    if (idx < TOK) { g_lns[idx] = 0.f; g_lnq[idx] = 0.f; }
    if (idx < 64) {
        g_g1s[idx] = 0.f; g_g1q[idx] = 0.f;
        g_g2s[idx] = 0.f; g_g2q[idx] = 0.f;
    }
}

// =====================================================================
// in_proj GEMM with fused BCHW gather + fused LN-stat partials.
// CTA 128x64, warp 32x32, kc=32. A^T smem [32][136].
// =====================================================================
__global__ __launch_bounds__(256, 4)
void k_tc_in(const float* __restrict__ X, const float* __restrict__ Hh,
             const float* __restrict__ W, const float* __restrict__ bias,
             float* __restrict__ C)
{
    constexpr int K = 256, NCH = 8;
    constexpr int MST = 136;
    constexpr int AST = 36;
    extern __shared__ float smf[];
    float* Asb[2] = { smf, smf + 32 * MST };
    float* Bsb[2] = { smf + 2 * 32 * MST, smf + 2 * 32 * MST + 64 * AST };

    const int tid  = threadIdx.x;
    const int lane = tid & 31;
    const int warp = tid >> 5;
    const int wm = warp & 3, wn = warp >> 2;
    const int m0 = blockIdx.y * 128;
    const int n0 = blockIdx.x * 64;
    const int b  = m0 >> 14;
    const int p0 = m0 & 16383;

    const uint32_t sA[2] = { smem_to_u32(Asb[0]), smem_to_u32(Asb[1]) };
    const uint32_t sB[2] = { smem_to_u32(Bsb[0]), smem_to_u32(Bsb[1]) };

    float acc[2][4][4];
#pragma unroll
    for (int i = 0; i < 2; i++)
#pragma unroll
        for (int j = 0; j < 4; j++)
#pragma unroll
            for (int q = 0; q < 4; q++) acc[i][j][q] = 0.f;

    auto prefetch = [&](int kt) {
        int buf = kt & 1;
#pragma unroll
        for (int j = 0; j < 4; j++) {
            int idx = tid + 256 * j;
            int k = idx >> 5, ms4 = idx & 31;
            int kg = kt * 32 + k;
            const float* src = (kg < 64)
                ? X  + (((size_t)(b * 64  + kg))        << 14) + p0 + ms4 * 4
                : Hh + (((size_t)(b * 192 + (kg - 64))) << 14) + p0 + ms4 * 4;
            CP_ASYNC16(sA[buf] + (uint32_t)(k * MST + ms4 * 4) * 4, src);
        }
        const float* bg = W + (size_t)n0 * K + kt * 32;
#pragma unroll
        for (int j = 0; j < 2; j++) {
            int idx = tid + 256 * j;
            int row = idx >> 3, off = idx & 7;
            CP_ASYNC16(sB[buf] + (uint32_t)(row * AST + off * 4) * 4,
                       bg + (size_t)row * K + off * 4);
        }
        CP_COMMIT();
    };

    prefetch(0);

    for (int kt = 0; kt < NCH; kt++) {
        if (kt + 1 < NCH) { prefetch(kt + 1); CP_WAIT(1); }
        else              { CP_WAIT(0); }
        __syncthreads();
        const float* as = Asb[kt & 1];
        const float* bs = Bsb[kt & 1];
#pragma unroll
        for (int ks = 0; ks < 4; ks++) {
            const int cc = ks * 8 + (lane & 3);
            uint32_t af[2][4];
#pragma unroll
            for (int mf = 0; mf < 2; mf++) {
                int r = wm * 32 + mf * 16 + (lane >> 2);
                af[mf][0] = __float_as_uint(as[cc * MST + r]);
                af[mf][1] = __float_as_uint(as[cc * MST + r + 8]);
                af[mf][2] = __float_as_uint(as[(cc + 4) * MST + r]);
                af[mf][3] = __float_as_uint(as[(cc + 4) * MST + r + 8]);
            }
            uint32_t bf[4][2];
#pragma unroll
            for (int nf = 0; nf < 4; nf++) {
                int rb = wn * 32 + nf * 8 + (lane >> 2);
                bf[nf][0] = __float_as_uint(bs[rb * AST + cc]);
                bf[nf][1] = __float_as_uint(bs[rb * AST + cc + 4]);
            }
#pragma unroll
            for (int mf = 0; mf < 2; mf++)
#pragma unroll
                for (int nf = 0; nf < 4; nf++)
                    mma_tf32(acc[mf][nf][0], acc[mf][nf][1], acc[mf][nf][2], acc[mf][nf][3],
                             af[mf][0], af[mf][1], af[mf][2], af[mf][3],
                             bf[nf][0], bf[nf][1]);
        }
        __syncthreads();
    }

    // epilogue: store + LN partials
    float rs[2][2] = {{0.f,0.f},{0.f,0.f}};
    float rq[2][2] = {{0.f,0.f},{0.f,0.f}};
#pragma unroll
    for (int mf = 0; mf < 2; mf++) {
        int row = m0 + wm * 32 + mf * 16 + (lane >> 2);
#pragma unroll
        for (int nf = 0; nf < 4; nf++) {
            int col = n0 + wn * 32 + nf * 8 + 2 * (lane & 3);
            float bx = bias[col], by = bias[col + 1];
            float2 o0 = make_float2(acc[mf][nf][0] + bx, acc[mf][nf][1] + by);
            float2 o1 = make_float2(acc[mf][nf][2] + bx, acc[mf][nf][3] + by);
            *reinterpret_cast<float2*>(&C[(size_t)row * 192 + col]) = o0;
            *reinterpret_cast<float2*>(&C[(size_t)(row + 8) * 192 + col]) = o1;
            rs[mf][0] += o0.x + o0.y;  rq[mf][0] += o0.x * o0.x + o0.y * o0.y;
            rs[mf][1] += o1.x + o1.y;  rq[mf][1] += o1.x * o1.x + o1.y * o1.y;
        }
    }
#pragma unroll
    for (int mf = 0; mf < 2; mf++)
#pragma unroll
        for (int half = 0; half < 2; half++) {
            float s = rs[mf][half], qq = rq[mf][half];
            s  += __shfl_xor_sync(0xffffffffu, s, 1);
            s  += __shfl_xor_sync(0xffffffffu, s, 2);
            qq += __shfl_xor_sync(0xffffffffu, qq, 1);
            qq += __shfl_xor_sync(0xffffffffu, qq, 2);
            if ((lane & 3) == 0) {
                int row = m0 + wm * 32 + mf * 16 + (lane >> 2) + 8 * half;
                atomicAdd(&g_lns[row], s);
                atomicAdd(&g_lnq[row], qq);
            }
        }
}

// =====================================================================
// qkv GEMM with fused LayerNorm on A (mu/iv computed in-kernel from
// the atomic sums, in-place smem transform). CTA 128x64, warp 32x32.
// =====================================================================
__global__ __launch_bounds__(256, 4)
void k_tcln(const float* __restrict__ A, const float* __restrict__ W,
            const float* __restrict__ bias, float* __restrict__ C, int Ntot,
            const float* __restrict__ cg, const float* __restrict__ cb)
{
    constexpr int K = 192, NCH = 6, AST = 36;
    extern __shared__ float smf[];
    float* Asb[2] = { smf, smf + 128 * AST };
    float* Bsb[2] = { smf + 2 * 128 * AST, smf + 2 * 128 * AST + 64 * AST };
    float* smu = smf + 2 * 128 * AST + 2 * 64 * AST;
    float* siv = smu + 128;

    const int tid  = threadIdx.x;
    const int lane = tid & 31;
    const int warp = tid >> 5;
    const int wm = warp & 3, wn = warp >> 2;
    const int m0 = blockIdx.y * 128;
    const int n0 = blockIdx.x * 64;
    const int arow = tid >> 3, aoff = tid & 7;

    const uint32_t sA[2] = { smem_to_u32(Asb[0]), smem_to_u32(Asb[1]) };
    const uint32_t sB[2] = { smem_to_u32(Bsb[0]), smem_to_u32(Bsb[1]) };

    if (tid < 128) {
        float s = g_lns[m0 + tid], qn = g_lnq[m0 + tid];
        float m = s * (1.0f / 192.0f);
        smu[tid] = m;
        siv[tid] = rsqrtf(qn * (1.0f / 192.0f) - m * m + 1e-5f);
    }

    float acc[2][4][4];
#pragma unroll
    for (int i = 0; i < 2; i++)
#pragma unroll
        for (int j = 0; j < 4; j++)
#pragma unroll
            for (int q = 0; q < 4; q++) acc[i][j][q] = 0.f;

    auto prefetch = [&](int kt) {
        int buf = kt & 1;
        const float* ag = A + (size_t)m0 * K + kt * 32;
        const float* bg = W + (size_t)n0 * K + kt * 32;
#pragma unroll
        for (int j = 0; j < 4; j++) {
            int idx = tid + 256 * j;
            int row = idx >> 3, off = idx & 7;
            CP_ASYNC16(sA[buf] + (uint32_t)(row * AST + off * 4) * 4,
                       ag + (size_t)row * K + off * 4);
        }
#pragma unroll
        for (int j = 0; j < 2; j++) {
            int idx = tid + 256 * j;
            int row = idx >> 3, off = idx & 7;
            CP_ASYNC16(sB[buf] + (uint32_t)(row * AST + off * 4) * 4,
                       bg + (size_t)row * K + off * 4);
        }
        CP_COMMIT();
    };

    prefetch(0);

    for (int kt = 0; kt < NCH; kt++) {
        if (kt + 1 < NCH) { prefetch(kt + 1); CP_WAIT(1); }
        else              { CP_WAIT(0); }
        __syncthreads();
        {   // in-place LayerNorm on A chunk
            float* as = Asb[kt & 1];
            const int k = kt * 32 + aoff * 4;
            float4 g4 = *reinterpret_cast<const float4*>(&cg[k]);
            float4 b4 = *reinterpret_cast<const float4*>(&cb[k]);
#pragma unroll
            for (int j = 0; j < 4; j++) {
                int row = arow + 32 * j;
                float mu = smu[row], iv = siv[row];
                float4 v = *reinterpret_cast<float4*>(&as[row * AST + aoff * 4]);
                v.x = (v.x - mu) * iv * g4.x + b4.x;
                v.y = (v.y - mu) * iv * g4.y + b4.y;
                v.z = (v.z - mu) * iv * g4.z + b4.z;
                v.w = (v.w - mu) * iv * g4.w + b4.w;
                *reinterpret_cast<float4*>(&as[row * AST + aoff * 4]) = v;
            }
        }
        __syncthreads();
        const float* as = Asb[kt & 1];
        const float* bs = Bsb[kt & 1];
#pragma unroll
        for (int ks = 0; ks < 4; ks++) {
            const int cc = ks * 8 + (lane & 3);
            uint32_t af[2][4];
#pragma unroll
            for (int mf = 0; mf < 2; mf++) {
                int r = wm * 32 + mf * 16 + (lane >> 2);
                af[mf][0] = __float_as_uint(as[r * AST + cc]);
                af[mf][1] = __float_as_uint(as[(r + 8) * AST + cc]);
                af[mf][2] = __float_as_uint(as[r * AST + cc + 4]);
                af[mf][3] = __float_as_uint(as[(r + 8) * AST + cc + 4]);
            }
            uint32_t bf[4][2];
#pragma unroll
            for (int nf = 0; nf < 4; nf++) {
                int rb = wn * 32 + nf * 8 + (lane >> 2);
                bf[nf][0] = __float_as_uint(bs[rb * AST + cc]);
                bf[nf][1] = __float_as_uint(bs[rb * AST + cc + 4]);
            }
#pragma unroll
            for (int mf = 0; mf < 2; mf++)
#pragma unroll
                for (int nf = 0; nf < 4; nf++)
                    mma_tf32(acc[mf][nf][0], acc[mf][nf][1], acc[mf][nf][2], acc[mf][nf][3],
                             af[mf][0], af[mf][1], af[mf][2], af[mf][3],
                             bf[nf][0], bf[nf][1]);
        }
        __syncthreads();
    }

#pragma unroll
    for (int mf = 0; mf < 2; mf++) {
        int row = m0 + wm * 32 + mf * 16 + (lane >> 2);
#pragma unroll
        for (int nf = 0; nf < 4; nf++) {
            int col = n0 + wn * 32 + nf * 8 + 2 * (lane & 3);
            float bx = bias[col], by = bias[col + 1];
            float2 o0 = make_float2(acc[mf][nf][0] + bx, acc[mf][nf][1] + by);
            float2 o1 = make_float2(acc[mf][nf][2] + bx, acc[mf][nf][3] + by);
            *reinterpret_cast<float2*>(&C[(size_t)row * Ntot + col]) = o0;
            *reinterpret_cast<float2*>(&C[(size_t)(row + 8) * Ntot + col]) = o1;
        }
    }
}

// =====================================================================
// out_proj GEMM + fused GN1 partial stats. CTA 128x64, warp 32x32.
// =====================================================================
__global__ __launch_bounds__(256, 4)
void k_tc2(const float* __restrict__ A, const float* __restrict__ W,
           const float* __restrict__ bias, float* __restrict__ C)
{
    constexpr int K = 192, NCH = 6, AST = 36;
    extern __shared__ float smf[];
    float* Asb[2] = { smf, smf + 128 * AST };
    float* Bsb[2] = { smf + 2 * 128 * AST, smf + 2 * 128 * AST + 64 * AST };

    const int tid  = threadIdx.x;
    const int lane = tid & 31;
    const int warp = tid >> 5;
    const int wm = warp & 3, wn = warp >> 2;
    const int m0 = blockIdx.y * 128;
    const int n0 = blockIdx.x * 64;

    const uint32_t sA[2] = { smem_to_u32(Asb[0]), smem_to_u32(Asb[1]) };
    const uint32_t sB[2] = { smem_to_u32(Bsb[0]), smem_to_u32(Bsb[1]) };

    float acc[2][4][4];
#pragma unroll
    for (int i = 0; i < 2; i++)
#pragma unroll
        for (int j = 0; j < 4; j++)
#pragma unroll
            for (int q = 0; q < 4; q++) acc[i][j][q] = 0.f;

    auto prefetch = [&](int kt) {
        int buf = kt & 1;
        const float* ag = A + (size_t)m0 * K + kt * 32;
        const float* bg = W + (size_t)n0 * K + kt * 32;
#pragma unroll
        for (int j = 0; j < 4; j++) {
            int idx = tid + 256 * j;
            int row = idx >> 3, off = idx & 7;
            CP_ASYNC16(sA[buf] + (uint32_t)(row * AST + off * 4) * 4,
                       ag + (size_t)row * K + off * 4);
        }
#pragma unroll
        for (int j = 0; j < 2; j++) {
            int idx = tid + 256 * j;
            int row = idx >> 3, off = idx & 7;
            CP_ASYNC16(sB[buf] + (uint32_t)(row * AST + off * 4) * 4,
                       bg + (size_t)row * K + off * 4);
        }
        CP_COMMIT();
    };

    prefetch(0);

    for (int kt = 0; kt < NCH; kt++) {
        if (kt + 1 < NCH) { prefetch(kt + 1); CP_WAIT(1); }
        else              { CP_WAIT(0); }
        __syncthreads();
        const float* as = Asb[kt & 1];
        const float* bs = Bsb[kt & 1];
#pragma unroll
        for (int ks = 0; ks < 4; ks++) {
            const int cc = ks * 8 + (lane & 3);
            uint32_t af[2][4];
#pragma unroll
            for (int mf = 0; mf < 2; mf++) {
                int r = wm * 32 + mf * 16 + (lane >> 2);
                af[mf][0] = __float_as_uint(as[r * AST + cc]);
                af[mf][1] = __float_as_uint(as[(r + 8) * AST + cc]);
                af[mf][2] = __float_as_uint(as[r * AST + cc + 4]);
                af[mf][3] = __float_as_uint(as[(r + 8) * AST + cc + 4]);
            }
            uint32_t bf[4][2];
#pragma unroll
            for (int nf = 0; nf < 4; nf++) {
                int rb = wn * 32 + nf * 8 + (lane >> 2);
                bf[nf][0] = __float_as_uint(bs[rb * AST + cc]);
                bf[nf][1] = __float_as_uint(bs[rb * AST + cc + 4]);
            }
#pragma unroll
            for (int mf = 0; mf < 2; mf++)
#pragma unroll
                for (int nf = 0; nf < 4; nf++)
                    mma_tf32(acc[mf][nf][0], acc[mf][nf][1], acc[mf][nf][2], acc[mf][nf][3],
                             af[mf][0], af[mf][1], af[mf][2], af[mf][3],
                             bf[nf][0], bf[nf][1]);
        }
        __syncthreads();
    }

    const int bb = m0 >> 14;
#pragma unroll
    for (int nf = 0; nf < 4; nf++) {
        float s = 0.f, qq = 0.f;
        int col = n0 + wn * 32 + nf * 8 + 2 * (lane & 3);
        float bx = bias[col], by = bias[col + 1];
#pragma unroll
        for (int mf = 0; mf < 2; mf++) {
            int row = m0 + wm * 32 + mf * 16 + (lane >> 2);
            float2 o0 = make_float2(acc[mf][nf][0] + bx, acc[mf][nf][1] + by);
            float2 o1 = make_float2(acc[mf][nf][2] + bx, acc[mf][nf][3] + by);
            *reinterpret_cast<float2*>(&C[(size_t)row * 192 + col]) = o0;
            *reinterpret_cast<float2*>(&C[(size_t)(row + 8) * 192 + col]) = o1;
            s  += o0.x + o0.y + o1.x + o1.y;
            qq += o0.x * o0.x + o0.y * o0.y + o1.x * o1.x + o1.y * o1.y;
        }
#pragma unroll
        for (int o = 16; o; o >>= 1) {
            s  += __shfl_xor_sync(0xffffffffu, s, o);
            qq += __shfl_xor_sync(0xffffffffu, qq, o);
        }
        if (lane == 0) {
            int g = (n0 + wn * 32 + nf * 8) / 24;
            atomicAdd(&g_g1s[bb * 8 + g], s);
            atomicAdd(&g_g1q[bb * 8 + g], qq);
        }
    }
}

// =====================================================================
// gates GEMM (permuted W) + register-space GN on A (S/T fold, GN1
// finalize done in-kernel) + LSTM epilogue + GN2 partial stats.
// =====================================================================
__global__ __launch_bounds__(256, 4)
void k_tcg(const float* __restrict__ A, const float* __restrict__ W,
           const float* __restrict__ bias,
           const float* __restrict__ cg, const float* __restrict__ cb,
           const float* __restrict__ Cin, float* __restrict__ out)
{
    constexpr int K = 192, NCH = 6, AST = 36;
    extern __shared__ float smf[];
    float* Asb[2] = { smf, smf + 128 * AST };
    float* Bsb[2] = { smf + 2 * 128 * AST, smf + 2 * 128 * AST + 64 * AST };
    float* sS = smf + 2 * 128 * AST + 2 * 64 * AST;
    float* sT = sS + 192;

    const int tid  = threadIdx.x;
    const int lane = tid & 31;
    const int warp = tid >> 5;
    const int wm = warp & 3, wn = warp >> 2;
    const int m0 = blockIdx.y * 128;
    const int n0 = blockIdx.x * 64;
    const int b8 = (m0 >> 14) << 3;

    const uint32_t sA[2] = { smem_to_u32(Asb[0]), smem_to_u32(Asb[1]) };
    const uint32_t sB[2] = { smem_to_u32(Bsb[0]), smem_to_u32(Bsb[1]) };

    if (tid < 192) {     // fold GN1 finalize: S[k], T[k]
        int grp = tid / 24;
        const float inv_n = 1.0f / 393216.0f;
        float m = g_g1s[b8 + grp] * inv_n;
        float iv = rsqrtf(g_g1q[b8 + grp] * inv_n - m * m + 1e-5f);
        float gv = cg[tid];
        sS[tid] = iv * gv;
        sT[tid] = cb[tid] - m * iv * gv;
    }

    float acc[2][4][4];
#pragma unroll
    for (int i = 0; i < 2; i++)
#pragma unroll
        for (int j = 0; j < 4; j++)
#pragma unroll
            for (int q = 0; q < 4; q++) acc[i][j][q] = 0.f;

    auto prefetch = [&](int kt) {
        int buf = kt & 1;
        const float* ag = A + (size_t)m0 * K + kt * 32;
        const float* bg = W + (size_t)n0 * K + kt * 32;
#pragma unroll
        for (int j = 0; j < 4; j++) {
            int idx = tid + 256 * j;
            int row = idx >> 3, off = idx & 7;
            CP_ASYNC16(sA[buf] + (uint32_t)(row * AST + off * 4) * 4,
                       ag + (size_t)row * K + off * 4);
        }
#pragma unroll
        for (int j = 0; j < 2; j++) {
            int idx = tid + 256 * j;
            int row = idx >> 3, off = idx & 7;
            CP_ASYNC16(sB[buf] + (uint32_t)(row * AST + off * 4) * 4,
                       bg + (size_t)row * K + off * 4);
        }
        CP_COMMIT();
    };

    prefetch(0);

    for (int kt = 0; kt < NCH; kt++) {
        if (kt + 1 < NCH) { prefetch(kt + 1); CP_WAIT(1); }
        else              { CP_WAIT(0); }
        __syncthreads();
        const float* as = Asb[kt & 1];
        const float* bs = Bsb[kt & 1];
#pragma unroll
        for (int ks = 0; ks < 4; ks++) {
            const int cc = ks * 8 + (lane & 3);
            const int kg = kt * 32 + cc;
            float S0 = sS[kg], T0 = sT[kg];
            float S1 = sS[kg + 4], T1 = sT[kg + 4];
            uint32_t af[2][4];
#pragma unroll
            for (int mf = 0; mf < 2; mf++) {
                int r = wm * 32 + mf * 16 + (lane >> 2);
                af[mf][0] = __float_as_uint(fmaf(as[r * AST + cc],       S0, T0));
                af[mf][1] = __float_as_uint(fmaf(as[(r + 8) * AST + cc], S0, T0));
                af[mf][2] = __float_as_uint(fmaf(as[r * AST + cc + 4],   S1, T1));
                af[mf][3] = __float_as_uint(fmaf(as[(r + 8) * AST + cc + 4], S1, T1));
            }
            uint32_t bf[4][2];
#pragma unroll
            for (int nf = 0; nf < 4; nf++) {
                int rb = wn * 32 + nf * 8 + (lane >> 2);
                bf[nf][0] = __float_as_uint(bs[rb * AST + cc]);
                bf[nf][1] = __float_as_uint(bs[rb * AST + cc + 4]);
            }
#pragma unroll
            for (int mf = 0; mf < 2; mf++)
#pragma unroll
                for (int nf = 0; nf < 4; nf++)
                    mma_tf32(acc[mf][nf][0], acc[mf][nf][1], acc[mf][nf][2], acc[mf][nf][3],
                             af[mf][0], af[mf][1], af[mf][2], af[mf][3],
                             bf[nf][0], bf[nf][1]);
        }
        __syncthreads();
    }

    // ---- LSTM epilogue + GN2 partials ----
    const int q = lane & 3;
    const int t = blockIdx.x;
    const int chA = t * 16 + wn * 8 + q;
    const int chB = chA + 4;
    const int colb = n0 + wn * 32 + 2 * q;
    float bIA = bias[colb + 0],  bFA = bias[colb + 1];
    float bOA = bias[colb + 8],  bGA = bias[colb + 9];
    float bIB = bias[colb + 16], bFB = bias[colb + 17];
    float bOB = bias[colb + 24], bGB = bias[colb + 25];

    const int bt = m0 >> 14;
    const size_t baseA = ((size_t)(bt * 192 + chA)) << 14;
    const size_t baseB = ((size_t)(bt * 192 + chB)) << 14;

    float sA_ = 0.f, qA_ = 0.f, sB_ = 0.f, qB_ = 0.f;
#pragma unroll
    for (int mf = 0; mf < 2; mf++) {
        int p = (m0 + wm * 32 + mf * 16 + (lane >> 2)) & 16383;
#pragma unroll
        for (int half = 0; half < 2; half++) {
            int pp = p + half * 8;
            int a0 = half * 2;
            {
                float gi = acc[mf][0][a0]     + bIA;
                float gf = acc[mf][0][a0 + 1] + bFA;
                float go = acc[mf][1][a0]     + bOA;
                float gg = acc[mf][1][a0 + 1] + bGA;
                float i_ = 1.f / (1.f + __expf(-gi));
                float f_ = 1.f / (1.f + __expf(-gf));
                float o_ = 1.f / (1.f + __expf(-go));
                float g_ = tanhf(gg);
                size_t addr = baseA + pp;
                float cn = f_ * Cin[addr] + i_ * g_;
                out[(size_t)HSZ + addr] = cn;
                float hv = o_ * tanhf(cn);
                g_hraw[addr] = hv;
                sA_ += hv; qA_ += hv * hv;
            }
            {
                float gi = acc[mf][2][a0]     + bIB;
                float gf = acc[mf][2][a0 + 1] + bFB;
                float go = acc[mf][3][a0]     + bOB;
                float gg = acc[mf][3][a0 + 1] + bGB;
                float i_ = 1.f / (1.f + __expf(-gi));
                float f_ = 1.f / (1.f + __expf(-gf));
                float o_ = 1.f / (1.f + __expf(-go));
                float g_ = tanhf(gg);
                size_t addr = baseB + pp;
                float cn = f_ * Cin[addr] + i_ * g_;
                out[(size_t)HSZ + addr] = cn;
                float hv = o_ * tanhf(cn);
                g_hraw[addr] = hv;
                sB_ += hv; qB_ += hv * hv;
            }
        }
    }
#pragma unroll
    for (int o = 16; o; o >>= 1) {
        sA_ += __shfl_xor_sync(0xffffffffu, sA_, o);
        qA_ += __shfl_xor_sync(0xffffffffu, qA_, o);
        sB_ += __shfl_xor_sync(0xffffffffu, sB_, o);
        qB_ += __shfl_xor_sync(0xffffffffu, qB_, o);
    }
    if (lane == 0) {
        int gA = (t * 16 + wn * 8) / 24;
        int gB = (t * 16 + wn * 8 + 4) / 24;
        atomicAdd(&g_g2s[bt * 8 + gA], sA_);
        atomicAdd(&g_g2q[bt * 8 + gA], qA_);
        atomicAdd(&g_g2s[bt * 8 + gB], sB_);
        atomicAdd(&g_g2q[bt * 8 + gB], qB_);
    }
}

// =====================================================================
// Window attention — K/V-only smem (XOR swizzle), Q direct from gmem,
// 4 windows/CTA, cp.async double-buffered, quad-shfl softmax.
// smem = 2*16*384*4 + 4096 = 53248 B -> 3 CTAs/SM.
// =====================================================================
#define KVS 384
__global__ __launch_bounds__(256, 3)
void k_attn()
{
    extern __shared__ float smf[];
    float* kv0 = smf;
    float* kv1 = smf + 16 * KVS;
    float* ss  = smf + 32 * KVS;       // 1024 floats

    const int tid = threadIdx.x;

    auto prefetch = [&](int w, float* buf) {
        int b = w >> 10, wi = w & 1023, wy = wi >> 5, wx = wi & 31;
        int rowbase = (b << 14) + (wy << 9) + (wx << 2);
        uint32_t sbase = smem_to_u32(buf);
#pragma unroll
        for (int j = 0; j < 6; j++) {
            int i = tid + 256 * j;
            int t = i / 96, c4 = i - t * 96;
            int tok = rowbase + ((t >> 2) << 7) + (t & 3);
            uint32_t dst = sbase + (uint32_t)(t * KVS + ((c4 ^ (t & 7)) << 2)) * 4;
            CP_ASYNC16(dst, &g_qkv[(size_t)tok * 576 + 192 + c4 * 4]);
        }
        CP_COMMIT();
    };

    const int w0 = blockIdx.x * 4;
    prefetch(w0, kv0);

    for (int it = 0; it < 4; it++) {
        if (it < 3) { prefetch(w0 + it + 1, (it & 1) ? kv0 : kv1); CP_WAIT(1); }
        else        { CP_WAIT(0); }
        __syncthreads();
        const float* kvb = (it & 1) ? kv1 : kv0;
        int w = w0 + it;
        int b = w >> 10, wi = w & 1023, wy = wi >> 5, wx = wi & 31;
        int rowbase = (b << 14) + (wy << 9) + (wx << 2);

        {   // scores + quad-shfl softmax; Q direct from gmem (broadcast in quad)
            int h = tid >> 6, r = (tid >> 2) & 15, cl = tid & 3;
            int tokq = rowbase + ((r >> 2) << 7) + (r & 3);
            const float4* qrow = reinterpret_cast<const float4*>(
                &g_qkv[(size_t)tokq * 576 + h * 48]);
            float4 qv[12];
#pragma unroll
            for (int k = 0; k < 12; k++) qv[k] = qrow[k];
            float d[4];
#pragma unroll
            for (int cc = 0; cc < 4; cc++) {
                int col = cl + 4 * cc;
                const float* krow = &kvb[col * KVS];
                int dl = col & 7;
                float dd = 0.f;
#pragma unroll
                for (int k = 0; k < 12; k++) {
                    float4 kvv = *reinterpret_cast<const float4*>(
                        &krow[((h * 12 + k) ^ dl) << 2]);
                    dd += qv[k].x * kvv.x + qv[k].y * kvv.y
                        + qv[k].z * kvv.z + qv[k].w * kvv.w;
                }
                d[cc] = dd * 0.14433756729740643f;
            }
            float mx = fmaxf(fmaxf(d[0], d[1]), fmaxf(d[2], d[3]));
            mx = fmaxf(mx, __shfl_xor_sync(0xffffffffu, mx, 1));
            mx = fmaxf(mx, __shfl_xor_sync(0xffffffffu, mx, 2));
            float e[4], sm = 0.f;
#pragma unroll
            for (int cc = 0; cc < 4; cc++) { e[cc] = __expf(d[cc] - mx); sm += e[cc]; }
            sm += __shfl_xor_sync(0xffffffffu, sm, 1);
            sm += __shfl_xor_sync(0xffffffffu, sm, 2);
            float rinv = 1.f / sm;
#pragma unroll
            for (int cc = 0; cc < 4; cc++)
                ss[(h * 16 + r) * 16 + cl + 4 * cc] = e[cc] * rinv;
        }
        __syncthreads();

        if (tid < 192) {      // AV: V float4 reused across 4 rows
            int c4 = tid % 48;
            int rp = tid / 48;
            int h = c4 / 12;
            float4 o[4];
#pragma unroll
            for (int rr = 0; rr < 4; rr++) o[rr] = make_float4(0.f, 0.f, 0.f, 0.f);
#pragma unroll
            for (int jj = 0; jj < 16; jj++) {
                float4 vv = *reinterpret_cast<const float4*>(
                    &kvb[jj * KVS + (((48 + c4) ^ (jj & 7)) << 2)]);
#pragma unroll
                for (int rr = 0; rr < 4; rr++) {
                    float sv = ss[(h * 16 + rp + rr * 4) * 16 + jj];
                    o[rr].x += sv * vv.x; o[rr].y += sv * vv.y;
                    o[rr].z += sv * vv.z; o[rr].w += sv * vv.w;
                }
            }
#pragma unroll
            for (int rr = 0; rr < 4; rr++) {
                int tok = rowbase + (rr << 7) + rp;
                *reinterpret_cast<float4*>(&g_attn[(size_t)tok * 192 + c4 * 4]) = o[rr];
            }
        }
        __syncthreads();      // protect ss + buffer for next iteration
    }
}

// =====================================================================
// final GN apply on hraw (GN2 finalize folded in)
// =====================================================================
__global__ __launch_bounds__(256)
void k_finalize(const float* __restrict__ gg, const float* __restrict__ gb,
                float* __restrict__ out)
{
    __shared__ float sp[2];
    size_t base0 = (size_t)blockIdx.x * 1024;
    if (threadIdx.x == 0) {
        int bc = (int)(base0 >> 14);
        int b = bc / 192, cch = bc - b * 192;
        int grp = cch / 24;
        const float inv_n = 1.0f / 393216.0f;
        float m = g_g2s[b * 8 + grp] * inv_n;
        float iv = rsqrtf(g_g2q[b * 8 + grp] * inv_n - m * m + 1e-5f);
        float sc = gg[cch] * iv;
        sp[0] = sc;
        sp[1] = gb[cch] - m * sc;
    }
    __syncthreads();
    float sc = sp[0], bi = sp[1];
    size_t base = base0 + (size_t)threadIdx.x * 4;
    float4 v = *reinterpret_cast<const float4*>(&g_hraw[base]);
    float4 o;
    o.x = v.x * sc + bi;
    o.y = v.y * sc + bi;
    o.z = v.z * sc + bi;
    o.w = v.w * sc + bi;
    *reinterpret_cast<float4*>(&out[base]) = o;
}

// =====================================================================
// host launcher
// =====================================================================
extern "C" void kernel_launch(void* const* d_in, const int* in_sizes, int n_in,
                              void* d_out, int out_size)
{
    const float* x       = (const float*)d_in[0];
    const float* h       = (const float*)d_in[1];
    const float* c       = (const float*)d_in[2];
    const float* w_in    = (const float*)d_in[3];
    const float* b_in    = (const float*)d_in[4];
    const float* ln_g    = (const float*)d_in[5];
    const float* ln_b    = (const float*)d_in[6];
    const float* w_qkv   = (const float*)d_in[7];
    const float* b_qkv   = (const float*)d_in[8];
    const float* w_proj  = (const float*)d_in[9];
    const float* b_proj  = (const float*)d_in[10];
    const float* gn_g    = (const float*)d_in[11];
    const float* gn_b    = (const float*)d_in[12];
    const float* w_gates = (const float*)d_in[13];
    const float* b_gates = (const float*)d_in[14];
    float* out = (float*)d_out;

    void *p_proj, *p_qkv, *p_attn, *p_amap, *p_wperm, *p_bperm;
    cudaGetSymbolAddress(&p_proj,  g_proj);
    cudaGetSymbolAddress(&p_qkv,   g_qkv);
    cudaGetSymbolAddress(&p_attn,  g_attn);
    cudaGetSymbolAddress(&p_amap,  g_amap);
    cudaGetSymbolAddress(&p_wperm, g_wperm);
    cudaGetSymbolAddress(&p_bperm, g_bperm);

    const int SM_TC = (2 * 128 + 2 * 64) * 36 * 4;                 // 55296
    const int SM_LN = SM_TC + 256 * 4;                             // 56320
    const int SM_GT = SM_TC + 384 * 4;                             // 56832
    const int SM_IN = (2 * 32 * 136 + 2 * 64 * 36) * 4;            // 53248
    const int SM_AT = (2 * 16 * KVS + 1024) * 4;                   // 53248
    cudaFuncSetAttribute(k_tcln, cudaFuncAttributeMaxDynamicSharedMemorySize, SM_LN);
    cudaFuncSetAttribute(k_tc2,  cudaFuncAttributeMaxDynamicSharedMemorySize, SM_TC);
    cudaFuncSetAttribute(k_tcg,  cudaFuncAttributeMaxDynamicSharedMemorySize, SM_GT);
    cudaFuncSetAttribute(k_tc_in, cudaFuncAttributeMaxDynamicSharedMemorySize, SM_IN);
    cudaFuncSetAttribute(k_attn, cudaFuncAttributeMaxDynamicSharedMemorySize, SM_AT);

    // 0) prep: permute gates weights + zero stat accumulators
    k_prep<<<768, 192>>>(w_gates, b_gates);
    // 1) in_proj GEMM (gather) + LN partial stats
    k_tc_in<<<dim3(3, 1024), 256, SM_IN>>>(x, h, w_in, b_in, (float*)p_proj);
    // 2) qkv GEMM with fused LayerNorm (lnfin folded, smem transform)
    k_tcln<<<dim3(9, 1024), 256, SM_LN>>>((const float*)p_proj, w_qkv, b_qkv,
                                          (float*)p_qkv, 576, ln_g, ln_b);
    // 3) window attention (K/V smem + Q gmem, 3 CTAs/SM)
    k_attn<<<2048, 256, SM_AT>>>();
    // 4) out_proj GEMM + GN1 partial stats
    k_tc2<<<dim3(3, 1024), 256, SM_TC>>>((const float*)p_attn, w_proj, b_proj,
                                         (float*)p_amap);
    // 5) gates GEMM + GN on A (gn1 finalize folded) + LSTM + GN2 partials
    k_tcg<<<dim3(12, 1024), 256, SM_GT>>>((const float*)p_amap, (const float*)p_wperm,
                                          (const float*)p_bperm,
                                          gn_g, gn_b, c, out);
    // 6) GN2 finalize + apply -> d_out first half
    k_finalize<<<24576, 256>>>(gn_g, gn_b, out);
}

// round 14
// speedup vs baseline: 1.0074x; 1.0074x over previous
#include <cuda_runtime.h>
#include <cstdint>

// ---------------- problem constants ----------------
#define TOK    131072              // B*H*W tokens (raster order)
#define HSZ    25165824            // 8*192*128*128 (one output tensor)

// ---------------- static device scratch ----------------
__device__ float g_proj[(size_t)TOK * 192];   // in_proj out (raw, pre-LN)
__device__ float g_qkv [(size_t)TOK * 576];
__device__ float g_attn[(size_t)TOK * 192];
__device__ float g_amap[(size_t)TOK * 192];   // out_proj out (raw, pre-GN)
__device__ float g_hraw[(size_t)TOK * 192];   // BCHW layout
__device__ float g_wperm[768 * 192];          // permuted gates weight
__device__ float g_bperm[768];
__device__ float g_lns[TOK], g_lnq[TOK];      // LN sums (atomic)
__device__ float g_g1s[64], g_g1q[64];        // GN1 sums (atomic)
__device__ float g_g2s[64], g_g2q[64];        // GN2 sums (atomic)

// ---------------- PTX helpers ----------------
#define CP_ASYNC16(sm, gp) \
    asm volatile("cp.async.cg.shared.global [%0], [%1], 16;" :: "r"((uint32_t)(sm)), "l"(gp))
#define CP_COMMIT() asm volatile("cp.async.commit_group;" ::: "memory")
#define CP_WAIT(n)  asm volatile("cp.async.wait_group %0;" :: "n"(n) : "memory")

__device__ __forceinline__ uint32_t smem_to_u32(const void* p) {
    uint32_t a;
    asm("{ .reg .u64 t; cvta.to.shared.u64 t, %1; cvt.u32.u64 %0, t; }" : "=r"(a) : "l"(p));
    return a;
}
__device__ __forceinline__ void mma_tf32(float& c0, float& c1, float& c2, float& c3,
                                         uint32_t a0, uint32_t a1, uint32_t a2, uint32_t a3,
                                         uint32_t b0, uint32_t b1) {
    asm volatile("mma.sync.aligned.m16n8k8.row.col.f32.tf32.tf32.f32 "
                 "{%0,%1,%2,%3}, {%4,%5,%6,%7}, {%8,%9}, {%0,%1,%2,%3};"
                 : "+f"(c0), "+f"(c1), "+f"(c2), "+f"(c3)
                 : "r"(a0), "r"(a1), "r"(a2), "r"(a3), "r"(b0), "r"(b1));
}

// =====================================================================
// prep: permute gates weight/bias + zero atomic accumulators
// =====================================================================
__global__ __launch_bounds__(192)
void k_prep(const float* __restrict__ wg, const float* __restrict__ bg)
{
    int col = blockIdx.x;
    int t = col >> 6, l = col & 63;
    int half = l >> 5, l2 = l & 31, b = l2 >> 4, l3 = l2 & 15;
    int ghi = l3 >> 3, l4 = l3 & 7, q = l4 >> 1, glo = l4 & 1;
    int gate = ghi * 2 + glo;
    int ch = t * 16 + half * 8 + b * 4 + q;
    int orow = gate * 192 + ch;
    g_wperm[col * 192 + threadIdx.x] = wg[orow * 192 + threadIdx.x];
    if (threadIdx.x == 0) g_bperm[col] = bg[orow];

    int idx = blockIdx.x * 192 + threadIdx.x;
    if (idx < TOK) { g_lns[idx] = 0.f; g_lnq[idx] = 0.f; }
    if (idx < 64) {
        g_g1s[idx] = 0.f; g_g1q[idx] = 0.f;
        g_g2s[idx] = 0.f; g_g2q[idx] = 0.f;
    }
}

// =====================================================================
// in_proj GEMM with fused BCHW gather + fused LN-stat partials.
// CTA 128x64, warp 32x32, kc=32. A^T smem [32][136].
// =====================================================================
__global__ __launch_bounds__(256, 4)
void k_tc_in(const float* __restrict__ X, const float* __restrict__ Hh,
             const float* __restrict__ W, const float* __restrict__ bias,
             float* __restrict__ C)
{
    constexpr int K = 256, NCH = 8;
    constexpr int MST = 136;
    constexpr int AST = 36;
    extern __shared__ float smf[];
    float* Asb[2] = { smf, smf + 32 * MST };
    float* Bsb[2] = { smf + 2 * 32 * MST, smf + 2 * 32 * MST + 64 * AST };

    const int tid  = threadIdx.x;
    const int lane = tid & 31;
    const int warp = tid >> 5;
    const int wm = warp & 3, wn = warp >> 2;
    const int m0 = blockIdx.y * 128;
    const int n0 = blockIdx.x * 64;
    const int b  = m0 >> 14;
    const int p0 = m0 & 16383;

    const uint32_t sA[2] = { smem_to_u32(Asb[0]), smem_to_u32(Asb[1]) };
    const uint32_t sB[2] = { smem_to_u32(Bsb[0]), smem_to_u32(Bsb[1]) };

    float acc[2][4][4];
#pragma unroll
    for (int i = 0; i < 2; i++)
#pragma unroll
        for (int j = 0; j < 4; j++)
#pragma unroll
            for (int q = 0; q < 4; q++) acc[i][j][q] = 0.f;

    auto prefetch = [&](int kt) {
        int buf = kt & 1;
#pragma unroll
        for (int j = 0; j < 4; j++) {
            int idx = tid + 256 * j;
            int k = idx >> 5, ms4 = idx & 31;
            int kg = kt * 32 + k;
            const float* src = (kg < 64)
                ? X  + (((size_t)(b * 64  + kg))        << 14) + p0 + ms4 * 4
                : Hh + (((size_t)(b * 192 + (kg - 64))) << 14) + p0 + ms4 * 4;
            CP_ASYNC16(sA[buf] + (uint32_t)(k * MST + ms4 * 4) * 4, src);
        }
        const float* bg = W + (size_t)n0 * K + kt * 32;
#pragma unroll
        for (int j = 0; j < 2; j++) {
            int idx = tid + 256 * j;
            int row = idx >> 3, off = idx & 7;
            CP_ASYNC16(sB[buf] + (uint32_t)(row * AST + off * 4) * 4,
                       bg + (size_t)row * K + off * 4);
        }
        CP_COMMIT();
    };

    prefetch(0);

    for (int kt = 0; kt < NCH; kt++) {
        if (kt + 1 < NCH) { prefetch(kt + 1); CP_WAIT(1); }
        else              { CP_WAIT(0); }
        __syncthreads();
        const float* as = Asb[kt & 1];
        const float* bs = Bsb[kt & 1];
#pragma unroll
        for (int ks = 0; ks < 4; ks++) {
            const int cc = ks * 8 + (lane & 3);
            uint32_t af[2][4];
#pragma unroll
            for (int mf = 0; mf < 2; mf++) {
                int r = wm * 32 + mf * 16 + (lane >> 2);
                af[mf][0] = __float_as_uint(as[cc * MST + r]);
                af[mf][1] = __float_as_uint(as[cc * MST + r + 8]);
                af[mf][2] = __float_as_uint(as[(cc + 4) * MST + r]);
                af[mf][3] = __float_as_uint(as[(cc + 4) * MST + r + 8]);
            }
            uint32_t bf[4][2];
#pragma unroll
            for (int nf = 0; nf < 4; nf++) {
                int rb = wn * 32 + nf * 8 + (lane >> 2);
                bf[nf][0] = __float_as_uint(bs[rb * AST + cc]);
                bf[nf][1] = __float_as_uint(bs[rb * AST + cc + 4]);
            }
#pragma unroll
            for (int mf = 0; mf < 2; mf++)
#pragma unroll
                for (int nf = 0; nf < 4; nf++)
                    mma_tf32(acc[mf][nf][0], acc[mf][nf][1], acc[mf][nf][2], acc[mf][nf][3],
                             af[mf][0], af[mf][1], af[mf][2], af[mf][3],
                             bf[nf][0], bf[nf][1]);
        }
        __syncthreads();
    }

    // epilogue: store + LN partials
    float rs[2][2] = {{0.f,0.f},{0.f,0.f}};
    float rq[2][2] = {{0.f,0.f},{0.f,0.f}};
#pragma unroll
    for (int mf = 0; mf < 2; mf++) {
        int row = m0 + wm * 32 + mf * 16 + (lane >> 2);
#pragma unroll
        for (int nf = 0; nf < 4; nf++) {
            int col = n0 + wn * 32 + nf * 8 + 2 * (lane & 3);
            float bx = bias[col], by = bias[col + 1];
            float2 o0 = make_float2(acc[mf][nf][0] + bx, acc[mf][nf][1] + by);
            float2 o1 = make_float2(acc[mf][nf][2] + bx, acc[mf][nf][3] + by);
            *reinterpret_cast<float2*>(&C[(size_t)row * 192 + col]) = o0;
            *reinterpret_cast<float2*>(&C[(size_t)(row + 8) * 192 + col]) = o1;
            rs[mf][0] += o0.x + o0.y;  rq[mf][0] += o0.x * o0.x + o0.y * o0.y;
            rs[mf][1] += o1.x + o1.y;  rq[mf][1] += o1.x * o1.x + o1.y * o1.y;
        }
    }
#pragma unroll
    for (int mf = 0; mf < 2; mf++)
#pragma unroll
        for (int half = 0; half < 2; half++) {
            float s = rs[mf][half], qq = rq[mf][half];
            s  += __shfl_xor_sync(0xffffffffu, s, 1);
            s  += __shfl_xor_sync(0xffffffffu, s, 2);
            qq += __shfl_xor_sync(0xffffffffu, qq, 1);
            qq += __shfl_xor_sync(0xffffffffu, qq, 2);
            if ((lane & 3) == 0) {
                int row = m0 + wm * 32 + mf * 16 + (lane >> 2) + 8 * half;
                atomicAdd(&g_lns[row], s);
                atomicAdd(&g_lnq[row], qq);
            }
        }
}

// =====================================================================
// qkv GEMM with fused LayerNorm on A (mu/iv computed in-kernel from
// the atomic sums, in-place smem transform). CTA 128x64, warp 32x32.
// =====================================================================
__global__ __launch_bounds__(256, 4)
void k_tcln(const float* __restrict__ A, const float* __restrict__ W,
            const float* __restrict__ bias, float* __restrict__ C, int Ntot,
            const float* __restrict__ cg, const float* __restrict__ cb)
{
    constexpr int K = 192, NCH = 6, AST = 36;
    extern __shared__ float smf[];
    float* Asb[2] = { smf, smf + 128 * AST };
    float* Bsb[2] = { smf + 2 * 128 * AST, smf + 2 * 128 * AST + 64 * AST };
    float* smu = smf + 2 * 128 * AST + 2 * 64 * AST;
    float* siv = smu + 128;

    const int tid  = threadIdx.x;
    const int lane = tid & 31;
    const int warp = tid >> 5;
    const int wm = warp & 3, wn = warp >> 2;
    const int m0 = blockIdx.y * 128;
    const int n0 = blockIdx.x * 64;
    const int arow = tid >> 3, aoff = tid & 7;

    const uint32_t sA[2] = { smem_to_u32(Asb[0]), smem_to_u32(Asb[1]) };
    const uint32_t sB[2] = { smem_to_u32(Bsb[0]), smem_to_u32(Bsb[1]) };

    if (tid < 128) {
        float s = g_lns[m0 + tid], qn = g_lnq[m0 + tid];
        float m = s * (1.0f / 192.0f);
        smu[tid] = m;
        siv[tid] = rsqrtf(qn * (1.0f / 192.0f) - m * m + 1e-5f);
    }

    float acc[2][4][4];
#pragma unroll
    for (int i = 0; i < 2; i++)
#pragma unroll
        for (int j = 0; j < 4; j++)
#pragma unroll
            for (int q = 0; q < 4; q++) acc[i][j][q] = 0.f;

    auto prefetch = [&](int kt) {
        int buf = kt & 1;
        const float* ag = A + (size_t)m0 * K + kt * 32;
        const float* bg = W + (size_t)n0 * K + kt * 32;
#pragma unroll
        for (int j = 0; j < 4; j++) {
            int idx = tid + 256 * j;
            int row = idx >> 3, off = idx & 7;
            CP_ASYNC16(sA[buf] + (uint32_t)(row * AST + off * 4) * 4,
                       ag + (size_t)row * K + off * 4);
        }
#pragma unroll
        for (int j = 0; j < 2; j++) {
            int idx = tid + 256 * j;
            int row = idx >> 3, off = idx & 7;
            CP_ASYNC16(sB[buf] + (uint32_t)(row * AST + off * 4) * 4,
                       bg + (size_t)row * K + off * 4);
        }
        CP_COMMIT();
    };

    prefetch(0);

    for (int kt = 0; kt < NCH; kt++) {
        if (kt + 1 < NCH) { prefetch(kt + 1); CP_WAIT(1); }
        else              { CP_WAIT(0); }
        __syncthreads();
        {   // in-place LayerNorm on A chunk
            float* as = Asb[kt & 1];
            const int k = kt * 32 + aoff * 4;
            float4 g4 = *reinterpret_cast<const float4*>(&cg[k]);
            float4 b4 = *reinterpret_cast<const float4*>(&cb[k]);
#pragma unroll
            for (int j = 0; j < 4; j++) {
                int row = arow + 32 * j;
                float mu = smu[row], iv = siv[row];
                float4 v = *reinterpret_cast<float4*>(&as[row * AST + aoff * 4]);
                v.x = (v.x - mu) * iv * g4.x + b4.x;
                v.y = (v.y - mu) * iv * g4.y + b4.y;
                v.z = (v.z - mu) * iv * g4.z + b4.z;
                v.w = (v.w - mu) * iv * g4.w + b4.w;
                *reinterpret_cast<float4*>(&as[row * AST + aoff * 4]) = v;
            }
        }
        __syncthreads();
        const float* as = Asb[kt & 1];
        const float* bs = Bsb[kt & 1];
#pragma unroll
        for (int ks = 0; ks < 4; ks++) {
            const int cc = ks * 8 + (lane & 3);
            uint32_t af[2][4];
#pragma unroll
            for (int mf = 0; mf < 2; mf++) {
                int r = wm * 32 + mf * 16 + (lane >> 2);
                af[mf][0] = __float_as_uint(as[r * AST + cc]);
                af[mf][1] = __float_as_uint(as[(r + 8) * AST + cc]);
                af[mf][2] = __float_as_uint(as[r * AST + cc + 4]);
                af[mf][3] = __float_as_uint(as[(r + 8) * AST + cc + 4]);
            }
            uint32_t bf[4][2];
#pragma unroll
            for (int nf = 0; nf < 4; nf++) {
                int rb = wn * 32 + nf * 8 + (lane >> 2);
                bf[nf][0] = __float_as_uint(bs[rb * AST + cc]);
                bf[nf][1] = __float_as_uint(bs[rb * AST + cc + 4]);
            }
#pragma unroll
            for (int mf = 0; mf < 2; mf++)
#pragma unroll
                for (int nf = 0; nf < 4; nf++)
                    mma_tf32(acc[mf][nf][0], acc[mf][nf][1], acc[mf][nf][2], acc[mf][nf][3],
                             af[mf][0], af[mf][1], af[mf][2], af[mf][3],
                             bf[nf][0], bf[nf][1]);
        }
        __syncthreads();
    }

#pragma unroll
    for (int mf = 0; mf < 2; mf++) {
        int row = m0 + wm * 32 + mf * 16 + (lane >> 2);
#pragma unroll
        for (int nf = 0; nf < 4; nf++) {
            int col = n0 + wn * 32 + nf * 8 + 2 * (lane & 3);
            float bx = bias[col], by = bias[col + 1];
            float2 o0 = make_float2(acc[mf][nf][0] + bx, acc[mf][nf][1] + by);
            float2 o1 = make_float2(acc[mf][nf][2] + bx, acc[mf][nf][3] + by);
            *reinterpret_cast<float2*>(&C[(size_t)row * Ntot + col]) = o0;
            *reinterpret_cast<float2*>(&C[(size_t)(row + 8) * Ntot + col]) = o1;
        }
    }
}

// =====================================================================
// out_proj GEMM + fused GN1 partial stats. CTA 128x64, warp 32x32.
// =====================================================================
__global__ __launch_bounds__(256, 4)
void k_tc2(const float* __restrict__ A, const float* __restrict__ W,
           const float* __restrict__ bias, float* __restrict__ C)
{
    constexpr int K = 192, NCH = 6, AST = 36;
    extern __shared__ float smf[];
    float* Asb[2] = { smf, smf + 128 * AST };
    float* Bsb[2] = { smf + 2 * 128 * AST, smf + 2 * 128 * AST + 64 * AST };

    const int tid  = threadIdx.x;
    const int lane = tid & 31;
    const int warp = tid >> 5;
    const int wm = warp & 3, wn = warp >> 2;
    const int m0 = blockIdx.y * 128;
    const int n0 = blockIdx.x * 64;

    const uint32_t sA[2] = { smem_to_u32(Asb[0]), smem_to_u32(Asb[1]) };
    const uint32_t sB[2] = { smem_to_u32(Bsb[0]), smem_to_u32(Bsb[1]) };

    float acc[2][4][4];
#pragma unroll
    for (int i = 0; i < 2; i++)
#pragma unroll
        for (int j = 0; j < 4; j++)
#pragma unroll
            for (int q = 0; q < 4; q++) acc[i][j][q] = 0.f;

    auto prefetch = [&](int kt) {
        int buf = kt & 1;
        const float* ag = A + (size_t)m0 * K + kt * 32;
        const float* bg = W + (size_t)n0 * K + kt * 32;
#pragma unroll
        for (int j = 0; j < 4; j++) {
            int idx = tid + 256 * j;
            int row = idx >> 3, off = idx & 7;
            CP_ASYNC16(sA[buf] + (uint32_t)(row * AST + off * 4) * 4,
                       ag + (size_t)row * K + off * 4);
        }
#pragma unroll
        for (int j = 0; j < 2; j++) {
            int idx = tid + 256 * j;
            int row = idx >> 3, off = idx & 7;
            CP_ASYNC16(sB[buf] + (uint32_t)(row * AST + off * 4) * 4,
                       bg + (size_t)row * K + off * 4);
        }
        CP_COMMIT();
    };

    prefetch(0);

    for (int kt = 0; kt < NCH; kt++) {
        if (kt + 1 < NCH) { prefetch(kt + 1); CP_WAIT(1); }
        else              { CP_WAIT(0); }
        __syncthreads();
        const float* as = Asb[kt & 1];
        const float* bs = Bsb[kt & 1];
#pragma unroll
        for (int ks = 0; ks < 4; ks++) {
            const int cc = ks * 8 + (lane & 3);
            uint32_t af[2][4];
#pragma unroll
            for (int mf = 0; mf < 2; mf++) {
                int r = wm * 32 + mf * 16 + (lane >> 2);
                af[mf][0] = __float_as_uint(as[r * AST + cc]);
                af[mf][1] = __float_as_uint(as[(r + 8) * AST + cc]);
                af[mf][2] = __float_as_uint(as[r * AST + cc + 4]);
                af[mf][3] = __float_as_uint(as[(r + 8) * AST + cc + 4]);
            }
            uint32_t bf[4][2];
#pragma unroll
            for (int nf = 0; nf < 4; nf++) {
                int rb = wn * 32 + nf * 8 + (lane >> 2);
                bf[nf][0] = __float_as_uint(bs[rb * AST + cc]);
                bf[nf][1] = __float_as_uint(bs[rb * AST + cc + 4]);
            }
#pragma unroll
            for (int mf = 0; mf < 2; mf++)
#pragma unroll
                for (int nf = 0; nf < 4; nf++)
                    mma_tf32(acc[mf][nf][0], acc[mf][nf][1], acc[mf][nf][2], acc[mf][nf][3],
                             af[mf][0], af[mf][1], af[mf][2], af[mf][3],
                             bf[nf][0], bf[nf][1]);
        }
        __syncthreads();
    }

    const int bb = m0 >> 14;
#pragma unroll
    for (int nf = 0; nf < 4; nf++) {
        float s = 0.f, qq = 0.f;
        int col = n0 + wn * 32 + nf * 8 + 2 * (lane & 3);
        float bx = bias[col], by = bias[col + 1];
#pragma unroll
        for (int mf = 0; mf < 2; mf++) {
            int row = m0 + wm * 32 + mf * 16 + (lane >> 2);
            float2 o0 = make_float2(acc[mf][nf][0] + bx, acc[mf][nf][1] + by);
            float2 o1 = make_float2(acc[mf][nf][2] + bx, acc[mf][nf][3] + by);
            *reinterpret_cast<float2*>(&C[(size_t)row * 192 + col]) = o0;
            *reinterpret_cast<float2*>(&C[(size_t)(row + 8) * 192 + col]) = o1;
            s  += o0.x + o0.y + o1.x + o1.y;
            qq += o0.x * o0.x + o0.y * o0.y + o1.x * o1.x + o1.y * o1.y;
        }
#pragma unroll
        for (int o = 16; o; o >>= 1) {
            s  += __shfl_xor_sync(0xffffffffu, s, o);
            qq += __shfl_xor_sync(0xffffffffu, qq, o);
        }
        if (lane == 0) {
            int g = (n0 + wn * 32 + nf * 8) / 24;
            atomicAdd(&g_g1s[bb * 8 + g], s);
            atomicAdd(&g_g1q[bb * 8 + g], qq);
        }
    }
}

// =====================================================================
// gates GEMM (permuted W) + register-space GN on A (S/T fold, GN1
// finalize done in-kernel) + LSTM epilogue + GN2 partial stats.
// =====================================================================
__global__ __launch_bounds__(256, 4)
void k_tcg(const float* __restrict__ A, const float* __restrict__ W,
           const float* __restrict__ bias,
           const float* __restrict__ cg, const float* __restrict__ cb,
           const float* __restrict__ Cin, float* __restrict__ out)
{
    constexpr int K = 192, NCH = 6, AST = 36;
    extern __shared__ float smf[];
    float* Asb[2] = { smf, smf + 128 * AST };
    float* Bsb[2] = { smf + 2 * 128 * AST, smf + 2 * 128 * AST + 64 * AST };
    float* sS = smf + 2 * 128 * AST + 2 * 64 * AST;
    float* sT = sS + 192;

    const int tid  = threadIdx.x;
    const int lane = tid & 31;
    const int warp = tid >> 5;
    const int wm = warp & 3, wn = warp >> 2;
    const int m0 = blockIdx.y * 128;
    const int n0 = blockIdx.x * 64;
    const int b8 = (m0 >> 14) << 3;

    const uint32_t sA[2] = { smem_to_u32(Asb[0]), smem_to_u32(Asb[1]) };
    const uint32_t sB[2] = { smem_to_u32(Bsb[0]), smem_to_u32(Bsb[1]) };

    if (tid < 192) {     // fold GN1 finalize: S[k], T[k]
        int grp = tid / 24;
        const float inv_n = 1.0f / 393216.0f;
        float m = g_g1s[b8 + grp] * inv_n;
        float iv = rsqrtf(g_g1q[b8 + grp] * inv_n - m * m + 1e-5f);
        float gv = cg[tid];
        sS[tid] = iv * gv;
        sT[tid] = cb[tid] - m * iv * gv;
    }

    float acc[2][4][4];
#pragma unroll
    for (int i = 0; i < 2; i++)
#pragma unroll
        for (int j = 0; j < 4; j++)
#pragma unroll
            for (int q = 0; q < 4; q++) acc[i][j][q] = 0.f;

    auto prefetch = [&](int kt) {
        int buf = kt & 1;
        const float* ag = A + (size_t)m0 * K + kt * 32;
        const float* bg = W + (size_t)n0 * K + kt * 32;
#pragma unroll
        for (int j = 0; j < 4; j++) {
            int idx = tid + 256 * j;
            int row = idx >> 3, off = idx & 7;
            CP_ASYNC16(sA[buf] + (uint32_t)(row * AST + off * 4) * 4,
                       ag + (size_t)row * K + off * 4);
        }
#pragma unroll
        for (int j = 0; j < 2; j++) {
            int idx = tid + 256 * j;
            int row = idx >> 3, off = idx & 7;
            CP_ASYNC16(sB[buf] + (uint32_t)(row * AST + off * 4) * 4,
                       bg + (size_t)row * K + off * 4);
        }
        CP_COMMIT();
    };

    prefetch(0);

    for (int kt = 0; kt < NCH; kt++) {
        if (kt + 1 < NCH) { prefetch(kt + 1); CP_WAIT(1); }
        else              { CP_WAIT(0); }
        __syncthreads();
        const float* as = Asb[kt & 1];
        const float* bs = Bsb[kt & 1];
#pragma unroll
        for (int ks = 0; ks < 4; ks++) {
            const int cc = ks * 8 + (lane & 3);
            const int kg = kt * 32 + cc;
            float S0 = sS[kg], T0 = sT[kg];
            float S1 = sS[kg + 4], T1 = sT[kg + 4];
            uint32_t af[2][4];
#pragma unroll
            for (int mf = 0; mf < 2; mf++) {
                int r = wm * 32 + mf * 16 + (lane >> 2);
                af[mf][0] = __float_as_uint(fmaf(as[r * AST + cc],       S0, T0));
                af[mf][1] = __float_as_uint(fmaf(as[(r + 8) * AST + cc], S0, T0));
                af[mf][2] = __float_as_uint(fmaf(as[r * AST + cc + 4],   S1, T1));
                af[mf][3] = __float_as_uint(fmaf(as[(r + 8) * AST + cc + 4], S1, T1));
            }
            uint32_t bf[4][2];
#pragma unroll
            for (int nf = 0; nf < 4; nf++) {
                int rb = wn * 32 + nf * 8 + (lane >> 2);
                bf[nf][0] = __float_as_uint(bs[rb * AST + cc]);
                bf[nf][1] = __float_as_uint(bs[rb * AST + cc + 4]);
            }
#pragma unroll
            for (int mf = 0; mf < 2; mf++)
#pragma unroll
                for (int nf = 0; nf < 4; nf++)
                    mma_tf32(acc[mf][nf][0], acc[mf][nf][1], acc[mf][nf][2], acc[mf][nf][3],
                             af[mf][0], af[mf][1], af[mf][2], af[mf][3],
                             bf[nf][0], bf[nf][1]);
        }
        __syncthreads();
    }

    // ---- LSTM epilogue + GN2 partials ----
    const int q = lane & 3;
    const int t = blockIdx.x;
    const int chA = t * 16 + wn * 8 + q;
    const int chB = chA + 4;
    const int colb = n0 + wn * 32 + 2 * q;
    float bIA = bias[colb + 0],  bFA = bias[colb + 1];
    float bOA = bias[colb + 8],  bGA = bias[colb + 9];
    float bIB = bias[colb + 16], bFB = bias[colb + 17];
    float bOB = bias[colb + 24], bGB = bias[colb + 25];

    const int bt = m0 >> 14;
    const size_t baseA = ((size_t)(bt * 192 + chA)) << 14;
    const size_t baseB = ((size_t)(bt * 192 + chB)) << 14;

    float sA_ = 0.f, qA_ = 0.f, sB_ = 0.f, qB_ = 0.f;
#pragma unroll
    for (int mf = 0; mf < 2; mf++) {
        int p = (m0 + wm * 32 + mf * 16 + (lane >> 2)) & 16383;
#pragma unroll
        for (int half = 0; half < 2; half++) {
            int pp = p + half * 8;
            int a0 = half * 2;
            {
                float gi = acc[mf][0][a0]     + bIA;
                float gf = acc[mf][0][a0 + 1] + bFA;
                float go = acc[mf][1][a0]     + bOA;
                float gg = acc[mf][1][a0 + 1] + bGA;
                float i_ = 1.f / (1.f + __expf(-gi));
                float f_ = 1.f / (1.f + __expf(-gf));
                float o_ = 1.f / (1.f + __expf(-go));
                float g_ = tanhf(gg);
                size_t addr = baseA + pp;
                float cn = f_ * Cin[addr] + i_ * g_;
                out[(size_t)HSZ + addr] = cn;
                float hv = o_ * tanhf(cn);
                g_hraw[addr] = hv;
                sA_ += hv; qA_ += hv * hv;
            }
            {
                float gi = acc[mf][2][a0]     + bIB;
                float gf = acc[mf][2][a0 + 1] + bFB;
                float go = acc[mf][3][a0]     + bOB;
                float gg = acc[mf][3][a0 + 1] + bGB;
                float i_ = 1.f / (1.f + __expf(-gi));
                float f_ = 1.f / (1.f + __expf(-gf));
                float o_ = 1.f / (1.f + __expf(-go));
                float g_ = tanhf(gg);
                size_t addr = baseB + pp;
                float cn = f_ * Cin[addr] + i_ * g_;
                out[(size_t)HSZ + addr] = cn;
                float hv = o_ * tanhf(cn);
                g_hraw[addr] = hv;
                sB_ += hv; qB_ += hv * hv;
            }
        }
    }
#pragma unroll
    for (int o = 16; o; o >>= 1) {
        sA_ += __shfl_xor_sync(0xffffffffu, sA_, o);
        qA_ += __shfl_xor_sync(0xffffffffu, qA_, o);
        sB_ += __shfl_xor_sync(0xffffffffu, sB_, o);
        qB_ += __shfl_xor_sync(0xffffffffu, qB_, o);
    }
    if (lane == 0) {
        int gA = (t * 16 + wn * 8) / 24;
        int gB = (t * 16 + wn * 8 + 4) / 24;
        atomicAdd(&g_g2s[bt * 8 + gA], sA_);
        atomicAdd(&g_g2q[bt * 8 + gA], qA_);
        atomicAdd(&g_g2s[bt * 8 + gB], sB_);
        atomicAdd(&g_g2q[bt * 8 + gB], qB_);
    }
}

// =====================================================================
// Window attention — 8 windows/CTA, cp.async double-buffered,
// softmax fused into score phase via quad shfl. (round-12 core)
// =====================================================================
#define QS 580
#define WPC 8
__global__ __launch_bounds__(256, 2)
void k_attn()
{
    extern __shared__ float smf[];
    float* sq0 = smf;
    float* sq1 = smf + 16 * QS;
    float* ss  = smf + 32 * QS;        // 1024 floats

    const int tid = threadIdx.x;

    auto prefetch = [&](int w, float* buf) {
        int b = w >> 10, wi = w & 1023, wy = wi >> 5, wx = wi & 31;
        int rowbase = (b << 14) + (wy << 9) + (wx << 2);
        uint32_t sbase = smem_to_u32(buf);
#pragma unroll
        for (int j = 0; j < 9; j++) {
            int i = tid + 256 * j;
            int t = i / 144, c4 = i - t * 144;
            int tok = rowbase + ((t >> 2) << 7) + (t & 3);
            CP_ASYNC16(sbase + (uint32_t)(t * QS + c4 * 4) * 4,
                       &g_qkv[(size_t)tok * 576 + c4 * 4]);
        }
        CP_COMMIT();
    };

    const int w0 = blockIdx.x * WPC;
    prefetch(w0, sq0);

    for (int it = 0; it < WPC; it++) {
        if (it < WPC - 1) { prefetch(w0 + it + 1, (it & 1) ? sq0 : sq1); CP_WAIT(1); }
        else              { CP_WAIT(0); }
        __syncthreads();
        const float* sqb = (it & 1) ? sq1 : sq0;
        int w = w0 + it;
        int b = w >> 10, wi = w & 1023, wy = wi >> 5, wx = wi & 31;
        int rowbase = (b << 14) + (wy << 9) + (wx << 2);

        {   // scores + quad-shfl softmax (row (h,r) spans lanes cl=0..3)
            int h = tid >> 6, r = (tid >> 2) & 15, cl = tid & 3;
            const float4* qrow = reinterpret_cast<const float4*>(&sqb[r * QS + h * 48]);
            float4 qv[12];
#pragma unroll
            for (int k = 0; k < 12; k++) qv[k] = qrow[k];
            float d[4];
#pragma unroll
            for (int cc = 0; cc < 4; cc++) {
                int col = cl + 4 * cc;
                const float4* krow = reinterpret_cast<const float4*>(
                    &sqb[col * QS + 192 + h * 48]);
                float dd = 0.f;
#pragma unroll
                for (int k = 0; k < 12; k++) {
                    float4 kv = krow[k];
                    dd += qv[k].x * kv.x + qv[k].y * kv.y + qv[k].z * kv.z + qv[k].w * kv.w;
                }
                d[cc] = dd * 0.14433756729740643f;
            }
            float mx = fmaxf(fmaxf(d[0], d[1]), fmaxf(d[2], d[3]));
            mx = fmaxf(mx, __shfl_xor_sync(0xffffffffu, mx, 1));
            mx = fmaxf(mx, __shfl_xor_sync(0xffffffffu, mx, 2));
            float e[4], sm = 0.f;
#pragma unroll
            for (int cc = 0; cc < 4; cc++) { e[cc] = __expf(d[cc] - mx); sm += e[cc]; }
            sm += __shfl_xor_sync(0xffffffffu, sm, 1);
            sm += __shfl_xor_sync(0xffffffffu, sm, 2);
            float rinv = 1.f / sm;
#pragma unroll
            for (int cc = 0; cc < 4; cc++)
                ss[(h * 16 + r) * 16 + cl + 4 * cc] = e[cc] * rinv;
        }
        __syncthreads();

        if (tid < 192) {      // AV: V float4 reused across 4 rows
            int c4 = tid % 48;
            int rp = tid / 48;
            int h = c4 / 12;
            const float* vbase = &sqb[384 + c4 * 4];
            float4 o[4];
#pragma unroll
            for (int rr = 0; rr < 4; rr++) o[rr] = make_float4(0.f, 0.f, 0.f, 0.f);
#pragma unroll
            for (int jj = 0; jj < 16; jj++) {
                float4 vv = *reinterpret_cast<const float4*>(&vbase[jj * QS]);
#pragma unroll
                for (int rr = 0; rr < 4; rr++) {
                    float sv = ss[(h * 16 + rp + rr * 4) * 16 + jj];
                    o[rr].x += sv * vv.x; o[rr].y += sv * vv.y;
                    o[rr].z += sv * vv.z; o[rr].w += sv * vv.w;
                }
            }
#pragma unroll
            for (int rr = 0; rr < 4; rr++) {
                int tok = rowbase + (rr << 7) + rp;
                *reinterpret_cast<float4*>(&g_attn[(size_t)tok * 192 + c4 * 4]) = o[rr];
            }
        }
        __syncthreads();      // protect ss + buffer for next iteration
    }
}

// =====================================================================
// final GN apply on hraw (GN2 finalize folded in)
// =====================================================================
__global__ __launch_bounds__(256)
void k_finalize(const float* __restrict__ gg, const float* __restrict__ gb,
                float* __restrict__ out)
{
    __shared__ float sp[2];
    size_t base0 = (size_t)blockIdx.x * 1024;
    if (threadIdx.x == 0) {
        int bc = (int)(base0 >> 14);
        int b = bc / 192, cch = bc - b * 192;
        int grp = cch / 24;
        const float inv_n = 1.0f / 393216.0f;
        float m = g_g2s[b * 8 + grp] * inv_n;
        float iv = rsqrtf(g_g2q[b * 8 + grp] * inv_n - m * m + 1e-5f);
        float sc = gg[cch] * iv;
        sp[0] = sc;
        sp[1] = gb[cch] - m * sc;
    }
    __syncthreads();
    float sc = sp[0], bi = sp[1];
    size_t base = base0 + (size_t)threadIdx.x * 4;
    float4 v = *reinterpret_cast<const float4*>(&g_hraw[base]);
    float4 o;
    o.x = v.x * sc + bi;
    o.y = v.y * sc + bi;
    o.z = v.z * sc + bi;
    o.w = v.w * sc + bi;
    *reinterpret_cast<float4*>(&out[base]) = o;
}

// =====================================================================
// host launcher
// =====================================================================
extern "C" void kernel_launch(void* const* d_in, const int* in_sizes, int n_in,
                              void* d_out, int out_size)
{
    const float* x       = (const float*)d_in[0];
    const float* h       = (const float*)d_in[1];
    const float* c       = (const float*)d_in[2];
    const float* w_in    = (const float*)d_in[3];
    const float* b_in    = (const float*)d_in[4];
    const float* ln_g    = (const float*)d_in[5];
    const float* ln_b    = (const float*)d_in[6];
    const float* w_qkv   = (const float*)d_in[7];
    const float* b_qkv   = (const float*)d_in[8];
    const float* w_proj  = (const float*)d_in[9];
    const float* b_proj  = (const float*)d_in[10];
    const float* gn_g    = (const float*)d_in[11];
    const float* gn_b    = (const float*)d_in[12];
    const float* w_gates = (const float*)d_in[13];
    const float* b_gates = (const float*)d_in[14];
    float* out = (float*)d_out;

    void *p_proj, *p_qkv, *p_attn, *p_amap, *p_wperm, *p_bperm;
    cudaGetSymbolAddress(&p_proj,  g_proj);
    cudaGetSymbolAddress(&p_qkv,   g_qkv);
    cudaGetSymbolAddress(&p_attn,  g_attn);
    cudaGetSymbolAddress(&p_amap,  g_amap);
    cudaGetSymbolAddress(&p_wperm, g_wperm);
    cudaGetSymbolAddress(&p_bperm, g_bperm);

    const int SM_TC = (2 * 128 + 2 * 64) * 36 * 4;                 // 55296
    const int SM_LN = SM_TC + 256 * 4;                             // 56320
    const int SM_GT = SM_TC + 384 * 4;                             // 56832
    const int SM_IN = (2 * 32 * 136 + 2 * 64 * 36) * 4;            // 53248
    const int SM_AT = (2 * 16 * QS + 1024) * 4;                    // 78336
    cudaFuncSetAttribute(k_tcln, cudaFuncAttributeMaxDynamicSharedMemorySize, SM_LN);
    cudaFuncSetAttribute(k_tc2,  cudaFuncAttributeMaxDynamicSharedMemorySize, SM_TC);
    cudaFuncSetAttribute(k_tcg,  cudaFuncAttributeMaxDynamicSharedMemorySize, SM_GT);
    cudaFuncSetAttribute(k_tc_in, cudaFuncAttributeMaxDynamicSharedMemorySize, SM_IN);
    cudaFuncSetAttribute(k_attn, cudaFuncAttributeMaxDynamicSharedMemorySize, SM_AT);

    // 0) prep: permute gates weights + zero stat accumulators
    k_prep<<<768, 192>>>(w_gates, b_gates);
    // 1) in_proj GEMM (gather) + LN partial stats
    k_tc_in<<<dim3(3, 1024), 256, SM_IN>>>(x, h, w_in, b_in, (float*)p_proj);
    // 2) qkv GEMM with fused LayerNorm (lnfin folded, smem transform)
    k_tcln<<<dim3(9, 1024), 256, SM_LN>>>((const float*)p_proj, w_qkv, b_qkv,
                                          (float*)p_qkv, 576, ln_g, ln_b);
    // 3) window attention (8 windows/CTA, shfl softmax)
    k_attn<<<1024, 256, SM_AT>>>();
    // 4) out_proj GEMM + GN1 partial stats
    k_tc2<<<dim3(3, 1024), 256, SM_TC>>>((const float*)p_attn, w_proj, b_proj,
                                         (float*)p_amap);
    // 5) gates GEMM + GN on A (gn1 finalize folded) + LSTM + GN2 partials
    k_tcg<<<dim3(12, 1024), 256, SM_GT>>>((const float*)p_amap, (const float*)p_wperm,
                                          (const float*)p_bperm,
                                          gn_g, gn_b, c, out);
    // 6) GN2 finalize + apply -> d_out first half
    k_finalize<<<24576, 256>>>(gn_g, gn_b, out);
}

// round 15
// speedup vs baseline: 1.0138x; 1.0063x over previous
#include <cuda_runtime.h>
#include <cstdint>

// ---------------- problem constants ----------------
#define TOK    131072              // B*H*W tokens (raster order)
#define HSZ    25165824            // 8*192*128*128 (one output tensor)

// ---------------- static device scratch ----------------
__device__ float g_proj[(size_t)TOK * 192];   // in_proj out (raw, pre-LN)
__device__ float g_qkv [(size_t)TOK * 576];
__device__ float g_attn[(size_t)TOK * 192];
__device__ float g_amap[(size_t)TOK * 192];   // out_proj out (raw, pre-GN)
__device__ float g_hraw[(size_t)TOK * 192];   // BCHW layout
__device__ float g_wperm[768 * 192];          // permuted gates weight
__device__ float g_bperm[768];
__device__ float g_lns[TOK], g_lnq[TOK];      // LN sums (atomic)
__device__ float g_g1s[64], g_g1q[64];        // GN1 sums (atomic)
__device__ float g_g2s[64], g_g2q[64];        // GN2 sums (atomic)

// ---------------- PTX helpers ----------------
#define CP_ASYNC16(sm, gp) \
    asm volatile("cp.async.cg.shared.global [%0], [%1], 16;" :: "r"((uint32_t)(sm)), "l"(gp))
#define CP_COMMIT() asm volatile("cp.async.commit_group;" ::: "memory")
#define CP_WAIT(n)  asm volatile("cp.async.wait_group %0;" :: "n"(n) : "memory")

__device__ __forceinline__ uint32_t smem_to_u32(const void* p) {
    uint32_t a;
    asm("{ .reg .u64 t; cvta.to.shared.u64 t, %1; cvt.u32.u64 %0, t; }" : "=r"(a) : "l"(p));
    return a;
}
__device__ __forceinline__ void mma_tf32(float& c0, float& c1, float& c2, float& c3,
                                         uint32_t a0, uint32_t a1, uint32_t a2, uint32_t a3,
                                         uint32_t b0, uint32_t b1) {
    asm volatile("mma.sync.aligned.m16n8k8.row.col.f32.tf32.tf32.f32 "
                 "{%0,%1,%2,%3}, {%4,%5,%6,%7}, {%8,%9}, {%0,%1,%2,%3};"
                 : "+f"(c0), "+f"(c1), "+f"(c2), "+f"(c3)
                 : "r"(a0), "r"(a1), "r"(a2), "r"(a3), "r"(b0), "r"(b1));
}

// =====================================================================
// prep: permute gates weight/bias + zero atomic accumulators
// =====================================================================
__global__ __launch_bounds__(192)
void k_prep(const float* __restrict__ wg, const float* __restrict__ bg)
{
    int col = blockIdx.x;
    int t = col >> 6, l = col & 63;
    int half = l >> 5, l2 = l & 31, b = l2 >> 4, l3 = l2 & 15;
    int ghi = l3 >> 3, l4 = l3 & 7, q = l4 >> 1, glo = l4 & 1;
    int gate = ghi * 2 + glo;
    int ch = t * 16 + half * 8 + b * 4 + q;
    int orow = gate * 192 + ch;
    g_wperm[col * 192 + threadIdx.x] = wg[orow * 192 + threadIdx.x];
    if (threadIdx.x == 0) g_bperm[col] = bg[orow];

    int idx = blockIdx.x * 192 + threadIdx.x;
    if (idx < TOK) { g_lns[idx] = 0.f; g_lnq[idx] = 0.f; }
    if (idx < 64) {
        g_g1s[idx] = 0.f; g_g1q[idx] = 0.f;
        g_g2s[idx] = 0.f; g_g2q[idx] = 0.f;
    }
}

// =====================================================================
// in_proj GEMM with fused BCHW gather + fused LN-stat partials.
// CTA 128x64, warp 32x32, kc=32. A^T smem [32][136].
// =====================================================================
__global__ __launch_bounds__(256, 4)
void k_tc_in(const float* __restrict__ X, const float* __restrict__ Hh,
             const float* __restrict__ W, const float* __restrict__ bias,
             float* __restrict__ C)
{
    constexpr int K = 256, NCH = 8;
    constexpr int MST = 136;
    constexpr int AST = 36;
    extern __shared__ float smf[];
    float* Asb[2] = { smf, smf + 32 * MST };
    float* Bsb[2] = { smf + 2 * 32 * MST, smf + 2 * 32 * MST + 64 * AST };

    const int tid  = threadIdx.x;
    const int lane = tid & 31;
    const int warp = tid >> 5;
    const int wm = warp & 3, wn = warp >> 2;
    const int m0 = blockIdx.y * 128;
    const int n0 = blockIdx.x * 64;
    const int b  = m0 >> 14;
    const int p0 = m0 & 16383;

    const uint32_t sA[2] = { smem_to_u32(Asb[0]), smem_to_u32(Asb[1]) };
    const uint32_t sB[2] = { smem_to_u32(Bsb[0]), smem_to_u32(Bsb[1]) };

    float acc[2][4][4];
#pragma unroll
    for (int i = 0; i < 2; i++)
#pragma unroll
        for (int j = 0; j < 4; j++)
#pragma unroll
            for (int q = 0; q < 4; q++) acc[i][j][q] = 0.f;

    auto prefetch = [&](int kt) {
        int buf = kt & 1;
#pragma unroll
        for (int j = 0; j < 4; j++) {
            int idx = tid + 256 * j;
            int k = idx >> 5, ms4 = idx & 31;
            int kg = kt * 32 + k;
            const float* src = (kg < 64)
                ? X  + (((size_t)(b * 64  + kg))        << 14) + p0 + ms4 * 4
                : Hh + (((size_t)(b * 192 + (kg - 64))) << 14) + p0 + ms4 * 4;
            CP_ASYNC16(sA[buf] + (uint32_t)(k * MST + ms4 * 4) * 4, src);
        }
        const float* bg = W + (size_t)n0 * K + kt * 32;
#pragma unroll
        for (int j = 0; j < 2; j++) {
            int idx = tid + 256 * j;
            int row = idx >> 3, off = idx & 7;
            CP_ASYNC16(sB[buf] + (uint32_t)(row * AST + off * 4) * 4,
                       bg + (size_t)row * K + off * 4);
        }
        CP_COMMIT();
    };

    prefetch(0);

    for (int kt = 0; kt < NCH; kt++) {
        if (kt + 1 < NCH) { prefetch(kt + 1); CP_WAIT(1); }
        else              { CP_WAIT(0); }
        __syncthreads();
        const float* as = Asb[kt & 1];
        const float* bs = Bsb[kt & 1];
#pragma unroll
        for (int ks = 0; ks < 4; ks++) {
            const int cc = ks * 8 + (lane & 3);
            uint32_t af[2][4];
#pragma unroll
            for (int mf = 0; mf < 2; mf++) {
                int r = wm * 32 + mf * 16 + (lane >> 2);
                af[mf][0] = __float_as_uint(as[cc * MST + r]);
                af[mf][1] = __float_as_uint(as[cc * MST + r + 8]);
                af[mf][2] = __float_as_uint(as[(cc + 4) * MST + r]);
                af[mf][3] = __float_as_uint(as[(cc + 4) * MST + r + 8]);
            }
            uint32_t bf[4][2];
#pragma unroll
            for (int nf = 0; nf < 4; nf++) {
                int rb = wn * 32 + nf * 8 + (lane >> 2);
                bf[nf][0] = __float_as_uint(bs[rb * AST + cc]);
                bf[nf][1] = __float_as_uint(bs[rb * AST + cc + 4]);
            }
#pragma unroll
            for (int mf = 0; mf < 2; mf++)
#pragma unroll
                for (int nf = 0; nf < 4; nf++)
                    mma_tf32(acc[mf][nf][0], acc[mf][nf][1], acc[mf][nf][2], acc[mf][nf][3],
                             af[mf][0], af[mf][1], af[mf][2], af[mf][3],
                             bf[nf][0], bf[nf][1]);
        }
        __syncthreads();
    }

    // epilogue: store + LN partials
    float rs[2][2] = {{0.f,0.f},{0.f,0.f}};
    float rq[2][2] = {{0.f,0.f},{0.f,0.f}};
#pragma unroll
    for (int mf = 0; mf < 2; mf++) {
        int row = m0 + wm * 32 + mf * 16 + (lane >> 2);
#pragma unroll
        for (int nf = 0; nf < 4; nf++) {
            int col = n0 + wn * 32 + nf * 8 + 2 * (lane & 3);
            float bx = bias[col], by = bias[col + 1];
            float2 o0 = make_float2(acc[mf][nf][0] + bx, acc[mf][nf][1] + by);
            float2 o1 = make_float2(acc[mf][nf][2] + bx, acc[mf][nf][3] + by);
            *reinterpret_cast<float2*>(&C[(size_t)row * 192 + col]) = o0;
            *reinterpret_cast<float2*>(&C[(size_t)(row + 8) * 192 + col]) = o1;
            rs[mf][0] += o0.x + o0.y;  rq[mf][0] += o0.x * o0.x + o0.y * o0.y;
            rs[mf][1] += o1.x + o1.y;  rq[mf][1] += o1.x * o1.x + o1.y * o1.y;
        }
    }
#pragma unroll
    for (int mf = 0; mf < 2; mf++)
#pragma unroll
        for (int half = 0; half < 2; half++) {
            float s = rs[mf][half], qq = rq[mf][half];
            s  += __shfl_xor_sync(0xffffffffu, s, 1);
            s  += __shfl_xor_sync(0xffffffffu, s, 2);
            qq += __shfl_xor_sync(0xffffffffu, qq, 1);
            qq += __shfl_xor_sync(0xffffffffu, qq, 2);
            if ((lane & 3) == 0) {
                int row = m0 + wm * 32 + mf * 16 + (lane >> 2) + 8 * half;
                atomicAdd(&g_lns[row], s);
                atomicAdd(&g_lnq[row], qq);
            }
        }
}

// =====================================================================
// qkv GEMM with fused LayerNorm on A (mu/iv computed in-kernel from
// the atomic sums, in-place smem transform). CTA 128x64, warp 32x32.
// =====================================================================
__global__ __launch_bounds__(256, 4)
void k_tcln(const float* __restrict__ A, const float* __restrict__ W,
            const float* __restrict__ bias, float* __restrict__ C, int Ntot,
            const float* __restrict__ cg, const float* __restrict__ cb)
{
    constexpr int K = 192, NCH = 6, AST = 36;
    extern __shared__ float smf[];
    float* Asb[2] = { smf, smf + 128 * AST };
    float* Bsb[2] = { smf + 2 * 128 * AST, smf + 2 * 128 * AST + 64 * AST };
    float* smu = smf + 2 * 128 * AST + 2 * 64 * AST;
    float* siv = smu + 128;

    const int tid  = threadIdx.x;
    const int lane = tid & 31;
    const int warp = tid >> 5;
    const int wm = warp & 3, wn = warp >> 2;
    const int m0 = blockIdx.y * 128;
    const int n0 = blockIdx.x * 64;
    const int arow = tid >> 3, aoff = tid & 7;

    const uint32_t sA[2] = { smem_to_u32(Asb[0]), smem_to_u32(Asb[1]) };
    const uint32_t sB[2] = { smem_to_u32(Bsb[0]), smem_to_u32(Bsb[1]) };

    if (tid < 128) {
        float s = g_lns[m0 + tid], qn = g_lnq[m0 + tid];
        float m = s * (1.0f / 192.0f);
        smu[tid] = m;
        siv[tid] = rsqrtf(qn * (1.0f / 192.0f) - m * m + 1e-5f);
    }

    float acc[2][4][4];
#pragma unroll
    for (int i = 0; i < 2; i++)
#pragma unroll
        for (int j = 0; j < 4; j++)
#pragma unroll
            for (int q = 0; q < 4; q++) acc[i][j][q] = 0.f;

    auto prefetch = [&](int kt) {
        int buf = kt & 1;
        const float* ag = A + (size_t)m0 * K + kt * 32;
        const float* bg = W + (size_t)n0 * K + kt * 32;
#pragma unroll
        for (int j = 0; j < 4; j++) {
            int idx = tid + 256 * j;
            int row = idx >> 3, off = idx & 7;
            CP_ASYNC16(sA[buf] + (uint32_t)(row * AST + off * 4) * 4,
                       ag + (size_t)row * K + off * 4);
        }
#pragma unroll
        for (int j = 0; j < 2; j++) {
            int idx = tid + 256 * j;
            int row = idx >> 3, off = idx & 7;
            CP_ASYNC16(sB[buf] + (uint32_t)(row * AST + off * 4) * 4,
                       bg + (size_t)row * K + off * 4);
        }
        CP_COMMIT();
    };

    prefetch(0);

    for (int kt = 0; kt < NCH; kt++) {
        if (kt + 1 < NCH) { prefetch(kt + 1); CP_WAIT(1); }
        else              { CP_WAIT(0); }
        __syncthreads();
        {   // in-place LayerNorm on A chunk
            float* as = Asb[kt & 1];
            const int k = kt * 32 + aoff * 4;
            float4 g4 = *reinterpret_cast<const float4*>(&cg[k]);
            float4 b4 = *reinterpret_cast<const float4*>(&cb[k]);
#pragma unroll
            for (int j = 0; j < 4; j++) {
                int row = arow + 32 * j;
                float mu = smu[row], iv = siv[row];
                float4 v = *reinterpret_cast<float4*>(&as[row * AST + aoff * 4]);
                v.x = (v.x - mu) * iv * g4.x + b4.x;
                v.y = (v.y - mu) * iv * g4.y + b4.y;
                v.z = (v.z - mu) * iv * g4.z + b4.z;
                v.w = (v.w - mu) * iv * g4.w + b4.w;
                *reinterpret_cast<float4*>(&as[row * AST + aoff * 4]) = v;
            }
        }
        __syncthreads();
        const float* as = Asb[kt & 1];
        const float* bs = Bsb[kt & 1];
#pragma unroll
        for (int ks = 0; ks < 4; ks++) {
            const int cc = ks * 8 + (lane & 3);
            uint32_t af[2][4];
#pragma unroll
            for (int mf = 0; mf < 2; mf++) {
                int r = wm * 32 + mf * 16 + (lane >> 2);
                af[mf][0] = __float_as_uint(as[r * AST + cc]);
                af[mf][1] = __float_as_uint(as[(r + 8) * AST + cc]);
                af[mf][2] = __float_as_uint(as[r * AST + cc + 4]);
                af[mf][3] = __float_as_uint(as[(r + 8) * AST + cc + 4]);
            }
            uint32_t bf[4][2];
#pragma unroll
            for (int nf = 0; nf < 4; nf++) {
                int rb = wn * 32 + nf * 8 + (lane >> 2);
                bf[nf][0] = __float_as_uint(bs[rb * AST + cc]);
                bf[nf][1] = __float_as_uint(bs[rb * AST + cc + 4]);
            }
#pragma unroll
            for (int mf = 0; mf < 2; mf++)
#pragma unroll
                for (int nf = 0; nf < 4; nf++)
                    mma_tf32(acc[mf][nf][0], acc[mf][nf][1], acc[mf][nf][2], acc[mf][nf][3],
                             af[mf][0], af[mf][1], af[mf][2], af[mf][3],
                             bf[nf][0], bf[nf][1]);
        }
        __syncthreads();
    }

#pragma unroll
    for (int mf = 0; mf < 2; mf++) {
        int row = m0 + wm * 32 + mf * 16 + (lane >> 2);
#pragma unroll
        for (int nf = 0; nf < 4; nf++) {
            int col = n0 + wn * 32 + nf * 8 + 2 * (lane & 3);
            float bx = bias[col], by = bias[col + 1];
            float2 o0 = make_float2(acc[mf][nf][0] + bx, acc[mf][nf][1] + by);
            float2 o1 = make_float2(acc[mf][nf][2] + bx, acc[mf][nf][3] + by);
            *reinterpret_cast<float2*>(&C[(size_t)row * Ntot + col]) = o0;
            *reinterpret_cast<float2*>(&C[(size_t)(row + 8) * Ntot + col]) = o1;
        }
    }
}

// =====================================================================
// out_proj GEMM + fused GN1 partial stats. CTA 128x64, warp 32x32.
// =====================================================================
__global__ __launch_bounds__(256, 4)
void k_tc2(const float* __restrict__ A, const float* __restrict__ W,
           const float* __restrict__ bias, float* __restrict__ C)
{
    constexpr int K = 192, NCH = 6, AST = 36;
    extern __shared__ float smf[];
    float* Asb[2] = { smf, smf + 128 * AST };
    float* Bsb[2] = { smf + 2 * 128 * AST, smf + 2 * 128 * AST + 64 * AST };

    const int tid  = threadIdx.x;
    const int lane = tid & 31;
    const int warp = tid >> 5;
    const int wm = warp & 3, wn = warp >> 2;
    const int m0 = blockIdx.y * 128;
    const int n0 = blockIdx.x * 64;

    const uint32_t sA[2] = { smem_to_u32(Asb[0]), smem_to_u32(Asb[1]) };
    const uint32_t sB[2] = { smem_to_u32(Bsb[0]), smem_to_u32(Bsb[1]) };

    float acc[2][4][4];
#pragma unroll
    for (int i = 0; i < 2; i++)
#pragma unroll
        for (int j = 0; j < 4; j++)
#pragma unroll
            for (int q = 0; q < 4; q++) acc[i][j][q] = 0.f;

    auto prefetch = [&](int kt) {
        int buf = kt & 1;
        const float* ag = A + (size_t)m0 * K + kt * 32;
        const float* bg = W + (size_t)n0 * K + kt * 32;
#pragma unroll
        for (int j = 0; j < 4; j++) {
            int idx = tid + 256 * j;
            int row = idx >> 3, off = idx & 7;
            CP_ASYNC16(sA[buf] + (uint32_t)(row * AST + off * 4) * 4,
                       ag + (size_t)row * K + off * 4);
        }
#pragma unroll
        for (int j = 0; j < 2; j++) {
            int idx = tid + 256 * j;
            int row = idx >> 3, off = idx & 7;
            CP_ASYNC16(sB[buf] + (uint32_t)(row * AST + off * 4) * 4,
                       bg + (size_t)row * K + off * 4);
        }
        CP_COMMIT();
    };

    prefetch(0);

    for (int kt = 0; kt < NCH; kt++) {
        if (kt + 1 < NCH) { prefetch(kt + 1); CP_WAIT(1); }
        else              { CP_WAIT(0); }
        __syncthreads();
        const float* as = Asb[kt & 1];
        const float* bs = Bsb[kt & 1];
#pragma unroll
        for (int ks = 0; ks < 4; ks++) {
            const int cc = ks * 8 + (lane & 3);
            uint32_t af[2][4];
#pragma unroll
            for (int mf = 0; mf < 2; mf++) {
                int r = wm * 32 + mf * 16 + (lane >> 2);
                af[mf][0] = __float_as_uint(as[r * AST + cc]);
                af[mf][1] = __float_as_uint(as[(r + 8) * AST + cc]);
                af[mf][2] = __float_as_uint(as[r * AST + cc + 4]);
                af[mf][3] = __float_as_uint(as[(r + 8) * AST + cc + 4]);
            }
            uint32_t bf[4][2];
#pragma unroll
            for (int nf = 0; nf < 4; nf++) {
                int rb = wn * 32 + nf * 8 + (lane >> 2);
                bf[nf][0] = __float_as_uint(bs[rb * AST + cc]);
                bf[nf][1] = __float_as_uint(bs[rb * AST + cc + 4]);
            }
#pragma unroll
            for (int mf = 0; mf < 2; mf++)
#pragma unroll
                for (int nf = 0; nf < 4; nf++)
                    mma_tf32(acc[mf][nf][0], acc[mf][nf][1], acc[mf][nf][2], acc[mf][nf][3],
                             af[mf][0], af[mf][1], af[mf][2], af[mf][3],
                             bf[nf][0], bf[nf][1]);
        }
        __syncthreads();
    }

    const int bb = m0 >> 14;
#pragma unroll
    for (int nf = 0; nf < 4; nf++) {
        float s = 0.f, qq = 0.f;
        int col = n0 + wn * 32 + nf * 8 + 2 * (lane & 3);
        float bx = bias[col], by = bias[col + 1];
#pragma unroll
        for (int mf = 0; mf < 2; mf++) {
            int row = m0 + wm * 32 + mf * 16 + (lane >> 2);
            float2 o0 = make_float2(acc[mf][nf][0] + bx, acc[mf][nf][1] + by);
            float2 o1 = make_float2(acc[mf][nf][2] + bx, acc[mf][nf][3] + by);
            *reinterpret_cast<float2*>(&C[(size_t)row * 192 + col]) = o0;
            *reinterpret_cast<float2*>(&C[(size_t)(row + 8) * 192 + col]) = o1;
            s  += o0.x + o0.y + o1.x + o1.y;
            qq += o0.x * o0.x + o0.y * o0.y + o1.x * o1.x + o1.y * o1.y;
        }
#pragma unroll
        for (int o = 16; o; o >>= 1) {
            s  += __shfl_xor_sync(0xffffffffu, s, o);
            qq += __shfl_xor_sync(0xffffffffu, qq, o);
        }
        if (lane == 0) {
            int g = (n0 + wn * 32 + nf * 8) / 24;
            atomicAdd(&g_g1s[bb * 8 + g], s);
            atomicAdd(&g_g1q[bb * 8 + g], qq);
        }
    }
}

// =====================================================================
// gates GEMM (permuted W) + register-space GN on A (S/T fold, GN1
// finalize done in-kernel) + LSTM epilogue + GN2 partial stats.
// =====================================================================
__global__ __launch_bounds__(256, 4)
void k_tcg(const float* __restrict__ A, const float* __restrict__ W,
           const float* __restrict__ bias,
           const float* __restrict__ cg, const float* __restrict__ cb,
           const float* __restrict__ Cin, float* __restrict__ out)
{
    constexpr int K = 192, NCH = 6, AST = 36;
    extern __shared__ float smf[];
    float* Asb[2] = { smf, smf + 128 * AST };
    float* Bsb[2] = { smf + 2 * 128 * AST, smf + 2 * 128 * AST + 64 * AST };
    float* sS = smf + 2 * 128 * AST + 2 * 64 * AST;
    float* sT = sS + 192;

    const int tid  = threadIdx.x;
    const int lane = tid & 31;
    const int warp = tid >> 5;
    const int wm = warp & 3, wn = warp >> 2;
    const int m0 = blockIdx.y * 128;
    const int n0 = blockIdx.x * 64;
    const int b8 = (m0 >> 14) << 3;

    const uint32_t sA[2] = { smem_to_u32(Asb[0]), smem_to_u32(Asb[1]) };
    const uint32_t sB[2] = { smem_to_u32(Bsb[0]), smem_to_u32(Bsb[1]) };

    if (tid < 192) {     // fold GN1 finalize: S[k], T[k]
        int grp = tid / 24;
        const float inv_n = 1.0f / 393216.0f;
        float m = g_g1s[b8 + grp] * inv_n;
        float iv = rsqrtf(g_g1q[b8 + grp] * inv_n - m * m + 1e-5f);
        float gv = cg[tid];
        sS[tid] = iv * gv;
        sT[tid] = cb[tid] - m * iv * gv;
    }

    float acc[2][4][4];
#pragma unroll
    for (int i = 0; i < 2; i++)
#pragma unroll
        for (int j = 0; j < 4; j++)
#pragma unroll
            for (int q = 0; q < 4; q++) acc[i][j][q] = 0.f;

    auto prefetch = [&](int kt) {
        int buf = kt & 1;
        const float* ag = A + (size_t)m0 * K + kt * 32;
        const float* bg = W + (size_t)n0 * K + kt * 32;
#pragma unroll
        for (int j = 0; j < 4; j++) {
            int idx = tid + 256 * j;
            int row = idx >> 3, off = idx & 7;
            CP_ASYNC16(sA[buf] + (uint32_t)(row * AST + off * 4) * 4,
                       ag + (size_t)row * K + off * 4);
        }
#pragma unroll
        for (int j = 0; j < 2; j++) {
            int idx = tid + 256 * j;
            int row = idx >> 3, off = idx & 7;
            CP_ASYNC16(sB[buf] + (uint32_t)(row * AST + off * 4) * 4,
                       bg + (size_t)row * K + off * 4);
        }
        CP_COMMIT();
    };

    prefetch(0);

    for (int kt = 0; kt < NCH; kt++) {
        if (kt + 1 < NCH) { prefetch(kt + 1); CP_WAIT(1); }
        else              { CP_WAIT(0); }
        __syncthreads();
        const float* as = Asb[kt & 1];
        const float* bs = Bsb[kt & 1];
#pragma unroll
        for (int ks = 0; ks < 4; ks++) {
            const int cc = ks * 8 + (lane & 3);
            const int kg = kt * 32 + cc;
            float S0 = sS[kg], T0 = sT[kg];
            float S1 = sS[kg + 4], T1 = sT[kg + 4];
            uint32_t af[2][4];
#pragma unroll
            for (int mf = 0; mf < 2; mf++) {
                int r = wm * 32 + mf * 16 + (lane >> 2);
                af[mf][0] = __float_as_uint(fmaf(as[r * AST + cc],       S0, T0));
                af[mf][1] = __float_as_uint(fmaf(as[(r + 8) * AST + cc], S0, T0));
                af[mf][2] = __float_as_uint(fmaf(as[r * AST + cc + 4],   S1, T1));
                af[mf][3] = __float_as_uint(fmaf(as[(r + 8) * AST + cc + 4], S1, T1));
            }
            uint32_t bf[4][2];
#pragma unroll
            for (int nf = 0; nf < 4; nf++) {
                int rb = wn * 32 + nf * 8 + (lane >> 2);
                bf[nf][0] = __float_as_uint(bs[rb * AST + cc]);
                bf[nf][1] = __float_as_uint(bs[rb * AST + cc + 4]);
            }
#pragma unroll
            for (int mf = 0; mf < 2; mf++)
#pragma unroll
                for (int nf = 0; nf < 4; nf++)
                    mma_tf32(acc[mf][nf][0], acc[mf][nf][1], acc[mf][nf][2], acc[mf][nf][3],
                             af[mf][0], af[mf][1], af[mf][2], af[mf][3],
                             bf[nf][0], bf[nf][1]);
        }
        __syncthreads();
    }

    // ---- LSTM epilogue + GN2 partials ----
    const int q = lane & 3;
    const int t = blockIdx.x;
    const int chA = t * 16 + wn * 8 + q;
    const int chB = chA + 4;
    const int colb = n0 + wn * 32 + 2 * q;
    float bIA = bias[colb + 0],  bFA = bias[colb + 1];
    float bOA = bias[colb + 8],  bGA = bias[colb + 9];
    float bIB = bias[colb + 16], bFB = bias[colb + 17];
    float bOB = bias[colb + 24], bGB = bias[colb + 25];

    const int bt = m0 >> 14;
    const size_t baseA = ((size_t)(bt * 192 + chA)) << 14;
    const size_t baseB = ((size_t)(bt * 192 + chB)) << 14;

    float sA_ = 0.f, qA_ = 0.f, sB_ = 0.f, qB_ = 0.f;
#pragma unroll
    for (int mf = 0; mf < 2; mf++) {
        int p = (m0 + wm * 32 + mf * 16 + (lane >> 2)) & 16383;
#pragma unroll
        for (int half = 0; half < 2; half++) {
            int pp = p + half * 8;
            int a0 = half * 2;
            {
                float gi = acc[mf][0][a0]     + bIA;
                float gf = acc[mf][0][a0 + 1] + bFA;
                float go = acc[mf][1][a0]     + bOA;
                float gg = acc[mf][1][a0 + 1] + bGA;
                float i_ = 1.f / (1.f + __expf(-gi));
                float f_ = 1.f / (1.f + __expf(-gf));
                float o_ = 1.f / (1.f + __expf(-go));
                float g_ = tanhf(gg);
                size_t addr = baseA + pp;
                float cn = f_ * Cin[addr] + i_ * g_;
                out[(size_t)HSZ + addr] = cn;
                float hv = o_ * tanhf(cn);
                g_hraw[addr] = hv;
                sA_ += hv; qA_ += hv * hv;
            }
            {
                float gi = acc[mf][2][a0]     + bIB;
                float gf = acc[mf][2][a0 + 1] + bFB;
                float go = acc[mf][3][a0]     + bOB;
                float gg = acc[mf][3][a0 + 1] + bGB;
                float i_ = 1.f / (1.f + __expf(-gi));
                float f_ = 1.f / (1.f + __expf(-gf));
                float o_ = 1.f / (1.f + __expf(-go));
                float g_ = tanhf(gg);
                size_t addr = baseB + pp;
                float cn = f_ * Cin[addr] + i_ * g_;
                out[(size_t)HSZ + addr] = cn;
                float hv = o_ * tanhf(cn);
                g_hraw[addr] = hv;
                sB_ += hv; qB_ += hv * hv;
            }
        }
    }
#pragma unroll
    for (int o = 16; o; o >>= 1) {
        sA_ += __shfl_xor_sync(0xffffffffu, sA_, o);
        qA_ += __shfl_xor_sync(0xffffffffu, qA_, o);
        sB_ += __shfl_xor_sync(0xffffffffu, sB_, o);
        qB_ += __shfl_xor_sync(0xffffffffu, qB_, o);
    }
    if (lane == 0) {
        int gA = (t * 16 + wn * 8) / 24;
        int gB = (t * 16 + wn * 8 + 4) / 24;
        atomicAdd(&g_g2s[bt * 8 + gA], sA_);
        atomicAdd(&g_g2q[bt * 8 + gA], qA_);
        atomicAdd(&g_g2s[bt * 8 + gB], sB_);
        atomicAdd(&g_g2q[bt * 8 + gB], qB_);
    }
}

// =====================================================================
// Window attention — 4 windows/CTA, cp.async double-buffered,
// softmax fused into score phase via quad shfl. (round-12 exact)
// =====================================================================
#define QS 580
__global__ __launch_bounds__(256, 2)
void k_attn()
{
    extern __shared__ float smf[];
    float* sq0 = smf;
    float* sq1 = smf + 16 * QS;
    float* ss  = smf + 32 * QS;        // 1024 floats

    const int tid = threadIdx.x;

    auto prefetch = [&](int w, float* buf) {
        int b = w >> 10, wi = w & 1023, wy = wi >> 5, wx = wi & 31;
        int rowbase = (b << 14) + (wy << 9) + (wx << 2);
        uint32_t sbase = smem_to_u32(buf);
#pragma unroll
        for (int j = 0; j < 9; j++) {
            int i = tid + 256 * j;
            int t = i / 144, c4 = i - t * 144;
            int tok = rowbase + ((t >> 2) << 7) + (t & 3);
            CP_ASYNC16(sbase + (uint32_t)(t * QS + c4 * 4) * 4,
                       &g_qkv[(size_t)tok * 576 + c4 * 4]);
        }
        CP_COMMIT();
    };

    const int w0 = blockIdx.x * 4;
    prefetch(w0, sq0);

    for (int it = 0; it < 4; it++) {
        if (it < 3) { prefetch(w0 + it + 1, (it & 1) ? sq0 : sq1); CP_WAIT(1); }
        else        { CP_WAIT(0); }
        __syncthreads();
        const float* sqb = (it & 1) ? sq1 : sq0;
        int w = w0 + it;
        int b = w >> 10, wi = w & 1023, wy = wi >> 5, wx = wi & 31;
        int rowbase = (b << 14) + (wy << 9) + (wx << 2);

        {   // scores + quad-shfl softmax (row (h,r) spans lanes cl=0..3)
            int h = tid >> 6, r = (tid >> 2) & 15, cl = tid & 3;
            const float4* qrow = reinterpret_cast<const float4*>(&sqb[r * QS + h * 48]);
            float4 qv[12];
#pragma unroll
            for (int k = 0; k < 12; k++) qv[k] = qrow[k];
            float d[4];
#pragma unroll
            for (int cc = 0; cc < 4; cc++) {
                int col = cl + 4 * cc;
                const float4* krow = reinterpret_cast<const float4*>(
                    &sqb[col * QS + 192 + h * 48]);
                float dd = 0.f;
#pragma unroll
                for (int k = 0; k < 12; k++) {
                    float4 kv = krow[k];
                    dd += qv[k].x * kv.x + qv[k].y * kv.y + qv[k].z * kv.z + qv[k].w * kv.w;
                }
                d[cc] = dd * 0.14433756729740643f;
            }
            float mx = fmaxf(fmaxf(d[0], d[1]), fmaxf(d[2], d[3]));
            mx = fmaxf(mx, __shfl_xor_sync(0xffffffffu, mx, 1));
            mx = fmaxf(mx, __shfl_xor_sync(0xffffffffu, mx, 2));
            float e[4], sm = 0.f;
#pragma unroll
            for (int cc = 0; cc < 4; cc++) { e[cc] = __expf(d[cc] - mx); sm += e[cc]; }
            sm += __shfl_xor_sync(0xffffffffu, sm, 1);
            sm += __shfl_xor_sync(0xffffffffu, sm, 2);
            float rinv = 1.f / sm;
#pragma unroll
            for (int cc = 0; cc < 4; cc++)
                ss[(h * 16 + r) * 16 + cl + 4 * cc] = e[cc] * rinv;
        }
        __syncthreads();

        if (tid < 192) {      // AV: V float4 reused across 4 rows
            int c4 = tid % 48;
            int rp = tid / 48;
            int h = c4 / 12;
            const float* vbase = &sqb[384 + c4 * 4];
            float4 o[4];
#pragma unroll
            for (int rr = 0; rr < 4; rr++) o[rr] = make_float4(0.f, 0.f, 0.f, 0.f);
#pragma unroll
            for (int jj = 0; jj < 16; jj++) {
                float4 vv = *reinterpret_cast<const float4*>(&vbase[jj * QS]);
#pragma unroll
                for (int rr = 0; rr < 4; rr++) {
                    float sv = ss[(h * 16 + rp + rr * 4) * 16 + jj];
                    o[rr].x += sv * vv.x; o[rr].y += sv * vv.y;
                    o[rr].z += sv * vv.z; o[rr].w += sv * vv.w;
                }
            }
#pragma unroll
            for (int rr = 0; rr < 4; rr++) {
                int tok = rowbase + (rr << 7) + rp;
                *reinterpret_cast<float4*>(&g_attn[(size_t)tok * 192 + c4 * 4]) = o[rr];
            }
        }
        __syncthreads();      // protect ss + buffer for next iteration
    }
}

// =====================================================================
// final GN apply on hraw (GN2 finalize folded in) — 4 float4/thread
// for MLP=4; block span 4096 floats stays within one (b,c) run.
// =====================================================================
__global__ __launch_bounds__(256)
void k_finalize(const float* __restrict__ gg, const float* __restrict__ gb,
                float* __restrict__ out)
{
    __shared__ float sp[2];
    size_t base0 = (size_t)blockIdx.x * 4096;
    if (threadIdx.x == 0) {
        int bc = (int)(base0 >> 14);
        int b = bc / 192, cch = bc - b * 192;
        int grp = cch / 24;
        const float inv_n = 1.0f / 393216.0f;
        float m = g_g2s[b * 8 + grp] * inv_n;
        float iv = rsqrtf(g_g2q[b * 8 + grp] * inv_n - m * m + 1e-5f);
        float sc = gg[cch] * iv;
        sp[0] = sc;
        sp[1] = gb[cch] - m * sc;
    }
    __syncthreads();
    float sc = sp[0], bi = sp[1];
    size_t base = base0 + (size_t)threadIdx.x * 4;
    float4 v0 = *reinterpret_cast<const float4*>(&g_hraw[base]);
    float4 v1 = *reinterpret_cast<const float4*>(&g_hraw[base + 1024]);
    float4 v2 = *reinterpret_cast<const float4*>(&g_hraw[base + 2048]);
    float4 v3 = *reinterpret_cast<const float4*>(&g_hraw[base + 3072]);
    float4 o0, o1, o2, o3;
    o0.x = v0.x * sc + bi; o0.y = v0.y * sc + bi; o0.z = v0.z * sc + bi; o0.w = v0.w * sc + bi;
    o1.x = v1.x * sc + bi; o1.y = v1.y * sc + bi; o1.z = v1.z * sc + bi; o1.w = v1.w * sc + bi;
    o2.x = v2.x * sc + bi; o2.y = v2.y * sc + bi; o2.z = v2.z * sc + bi; o2.w = v2.w * sc + bi;
    o3.x = v3.x * sc + bi; o3.y = v3.y * sc + bi; o3.z = v3.z * sc + bi; o3.w = v3.w * sc + bi;
    *reinterpret_cast<float4*>(&out[base])        = o0;
    *reinterpret_cast<float4*>(&out[base + 1024]) = o1;
    *reinterpret_cast<float4*>(&out[base + 2048]) = o2;
    *reinterpret_cast<float4*>(&out[base + 3072]) = o3;
}

// =====================================================================
// host launcher
// =====================================================================
extern "C" void kernel_launch(void* const* d_in, const int* in_sizes, int n_in,
                              void* d_out, int out_size)
{
    const float* x       = (const float*)d_in[0];
    const float* h       = (const float*)d_in[1];
    const float* c       = (const float*)d_in[2];
    const float* w_in    = (const float*)d_in[3];
    const float* b_in    = (const float*)d_in[4];
    const float* ln_g    = (const float*)d_in[5];
    const float* ln_b    = (const float*)d_in[6];
    const float* w_qkv   = (const float*)d_in[7];
    const float* b_qkv   = (const float*)d_in[8];
    const float* w_proj  = (const float*)d_in[9];
    const float* b_proj  = (const float*)d_in[10];
    const float* gn_g    = (const float*)d_in[11];
    const float* gn_b    = (const float*)d_in[12];
    const float* w_gates = (const float*)d_in[13];
    const float* b_gates = (const float*)d_in[14];
    float* out = (float*)d_out;

    void *p_proj, *p_qkv, *p_attn, *p_amap, *p_wperm, *p_bperm;
    cudaGetSymbolAddress(&p_proj,  g_proj);
    cudaGetSymbolAddress(&p_qkv,   g_qkv);
    cudaGetSymbolAddress(&p_attn,  g_attn);
    cudaGetSymbolAddress(&p_amap,  g_amap);
    cudaGetSymbolAddress(&p_wperm, g_wperm);
    cudaGetSymbolAddress(&p_bperm, g_bperm);

    const int SM_TC = (2 * 128 + 2 * 64) * 36 * 4;                 // 55296
    const int SM_LN = SM_TC + 256 * 4;                             // 56320
    const int SM_GT = SM_TC + 384 * 4;                             // 56832
    const int SM_IN = (2 * 32 * 136 + 2 * 64 * 36) * 4;            // 53248
    const int SM_AT = (2 * 16 * QS + 1024) * 4;                    // 78336
    cudaFuncSetAttribute(k_tcln, cudaFuncAttributeMaxDynamicSharedMemorySize, SM_LN);
    cudaFuncSetAttribute(k_tc2,  cudaFuncAttributeMaxDynamicSharedMemorySize, SM_TC);
    cudaFuncSetAttribute(k_tcg,  cudaFuncAttributeMaxDynamicSharedMemorySize, SM_GT);
    cudaFuncSetAttribute(k_tc_in, cudaFuncAttributeMaxDynamicSharedMemorySize, SM_IN);
    cudaFuncSetAttribute(k_attn, cudaFuncAttributeMaxDynamicSharedMemorySize, SM_AT);

    // 0) prep: permute gates weights + zero stat accumulators
    k_prep<<<768, 192>>>(w_gates, b_gates);
    // 1) in_proj GEMM (gather) + LN partial stats
    k_tc_in<<<dim3(3, 1024), 256, SM_IN>>>(x, h, w_in, b_in, (float*)p_proj);
    // 2) qkv GEMM with fused LayerNorm (lnfin folded, smem transform)
    k_tcln<<<dim3(9, 1024), 256, SM_LN>>>((const float*)p_proj, w_qkv, b_qkv,
                                          (float*)p_qkv, 576, ln_g, ln_b);
    // 3) window attention (4 windows/CTA, shfl softmax)
    k_attn<<<2048, 256, SM_AT>>>();
    // 4) out_proj GEMM + GN1 partial stats
    k_tc2<<<dim3(3, 1024), 256, SM_TC>>>((const float*)p_attn, w_proj, b_proj,
                                         (float*)p_amap);
    // 5) gates GEMM + GN on A (gn1 finalize folded) + LSTM + GN2 partials
    k_tcg<<<dim3(12, 1024), 256, SM_GT>>>((const float*)p_amap, (const float*)p_wperm,
                                          (const float*)p_bperm,
                                          gn_g, gn_b, c, out);
    // 6) GN2 finalize + apply -> d_out first half (4 float4/thread)
    k_finalize<<<6144, 256>>>(gn_g, gn_b, out);
}

// round 17
// speedup vs baseline: 1.0345x; 1.0204x over previous
#include <cuda_runtime.h>
#include <cuda_fp16.h>
#include <cstdint>

// ---------------- problem constants ----------------
#define TOK    131072              // B*H*W tokens (raster order)
#define HSZ    25165824            // 8*192*128*128 (one output tensor)

// ---------------- static device scratch ----------------
__device__ float  g_proj[(size_t)TOK * 192];   // in_proj out (raw, pre-LN)
__device__ __half g_qkvh[(size_t)TOK * 576];   // qkv in fp16
__device__ float  g_attn[(size_t)TOK * 192];
__device__ float  g_amap[(size_t)TOK * 192];   // out_proj out (raw, pre-GN)
__device__ float  g_hraw[(size_t)TOK * 192];   // BCHW layout
__device__ float  g_wperm[768 * 192];          // permuted gates weight
__device__ float  g_bperm[768];
__device__ float  g_lns[TOK], g_lnq[TOK];      // LN sums (atomic)
__device__ float  g_g1s[64], g_g1q[64];        // GN1 sums (atomic)
__device__ float  g_g2s[64], g_g2q[64];        // GN2 sums (atomic)

// ---------------- PTX helpers ----------------
#define CP_ASYNC16(sm, gp) \
    asm volatile("cp.async.cg.shared.global [%0], [%1], 16;" :: "r"((uint32_t)(sm)), "l"(gp))
#define CP_COMMIT() asm volatile("cp.async.commit_group;" ::: "memory")
#define CP_WAIT(n)  asm volatile("cp.async.wait_group %0;" :: "n"(n) : "memory")

__device__ __forceinline__ uint32_t smem_to_u32(const void* p) {
    uint32_t a;
    asm("{ .reg .u64 t; cvta.to.shared.u64 t, %1; cvt.u32.u64 %0, t; }" : "=r"(a) : "l"(p));
    return a;
}
__device__ __forceinline__ void mma_tf32(float& c0, float& c1, float& c2, float& c3,
                                         uint32_t a0, uint32_t a1, uint32_t a2, uint32_t a3,
                                         uint32_t b0, uint32_t b1) {
    asm volatile("mma.sync.aligned.m16n8k8.row.col.f32.tf32.tf32.f32 "
                 "{%0,%1,%2,%3}, {%4,%5,%6,%7}, {%8,%9}, {%0,%1,%2,%3};"
                 : "+f"(c0), "+f"(c1), "+f"(c2), "+f"(c3)
                 : "r"(a0), "r"(a1), "r"(a2), "r"(a3), "r"(b0), "r"(b1));
}
__device__ __forceinline__ void h8_to_f8(uint4 u, float* f) {
    float2 t;
    t = __half22float2(*reinterpret_cast<__half2*>(&u.x)); f[0] = t.x; f[1] = t.y;
    t = __half22float2(*reinterpret_cast<__half2*>(&u.y)); f[2] = t.x; f[3] = t.y;
    t = __half22float2(*reinterpret_cast<__half2*>(&u.z)); f[4] = t.x; f[5] = t.y;
    t = __half22float2(*reinterpret_cast<__half2*>(&u.w)); f[6] = t.x; f[7] = t.y;
}

// =====================================================================
// prep: permute gates weight/bias + zero atomic accumulators
// =====================================================================
__global__ __launch_bounds__(192)
void k_prep(const float* __restrict__ wg, const float* __restrict__ bg)
{
    int col = blockIdx.x;
    int t = col >> 6, l = col & 63;
    int half = l >> 5, l2 = l & 31, b = l2 >> 4, l3 = l2 & 15;
    int ghi = l3 >> 3, l4 = l3 & 7, q = l4 >> 1, glo = l4 & 1;
    int gate = ghi * 2 + glo;
    int ch = t * 16 + half * 8 + b * 4 + q;
    int orow = gate * 192 + ch;
    g_wperm[col * 192 + threadIdx.x] = wg[orow * 192 + threadIdx.x];
    if (threadIdx.x == 0) g_bperm[col] = bg[orow];

    int idx = blockIdx.x * 192 + threadIdx.x;
    if (idx < TOK) { g_lns[idx] = 0.f; g_lnq[idx] = 0.f; }
    if (idx < 64) {
        g_g1s[idx] = 0.f; g_g1q[idx] = 0.f;
        g_g2s[idx] = 0.f; g_g2q[idx] = 0.f;
    }
}

// =====================================================================
// in_proj GEMM with fused BCHW gather + fused LN-stat partials.
// CTA 128x64, warp 32x32, kc=32. A^T smem [32][136].
// =====================================================================
__global__ __launch_bounds__(256, 4)
void k_tc_in(const float* __restrict__ X, const float* __restrict__ Hh,
             const float* __restrict__ W, const float* __restrict__ bias,
             float* __restrict__ C)
{
    constexpr int K = 256, NCH = 8;
    constexpr int MST = 136;
    constexpr int AST = 36;
    extern __shared__ float smf[];
    float* Asb[2] = { smf, smf + 32 * MST };
    float* Bsb[2] = { smf + 2 * 32 * MST, smf + 2 * 32 * MST + 64 * AST };

    const int tid  = threadIdx.x;
    const int lane = tid & 31;
    const int warp = tid >> 5;
    const int wm = warp & 3, wn = warp >> 2;
    const int m0 = blockIdx.y * 128;
    const int n0 = blockIdx.x * 64;
    const int b  = m0 >> 14;
    const int p0 = m0 & 16383;

    const uint32_t sA[2] = { smem_to_u32(Asb[0]), smem_to_u32(Asb[1]) };
    const uint32_t sB[2] = { smem_to_u32(Bsb[0]), smem_to_u32(Bsb[1]) };

    float acc[2][4][4];
#pragma unroll
    for (int i = 0; i < 2; i++)
#pragma unroll
        for (int j = 0; j < 4; j++)
#pragma unroll
            for (int q = 0; q < 4; q++) acc[i][j][q] = 0.f;

    auto prefetch = [&](int kt) {
        int buf = kt & 1;
#pragma unroll
        for (int j = 0; j < 4; j++) {
            int idx = tid + 256 * j;
            int k = idx >> 5, ms4 = idx & 31;
            int kg = kt * 32 + k;
            const float* src = (kg < 64)
                ? X  + (((size_t)(b * 64  + kg))        << 14) + p0 + ms4 * 4
                : Hh + (((size_t)(b * 192 + (kg - 64))) << 14) + p0 + ms4 * 4;
            CP_ASYNC16(sA[buf] + (uint32_t)(k * MST + ms4 * 4) * 4, src);
        }
        const float* bg = W + (size_t)n0 * K + kt * 32;
#pragma unroll
        for (int j = 0; j < 2; j++) {
            int idx = tid + 256 * j;
            int row = idx >> 3, off = idx & 7;
            CP_ASYNC16(sB[buf] + (uint32_t)(row * AST + off * 4) * 4,
                       bg + (size_t)row * K + off * 4);
        }
        CP_COMMIT();
    };

    prefetch(0);

    for (int kt = 0; kt < NCH; kt++) {
        if (kt + 1 < NCH) { prefetch(kt + 1); CP_WAIT(1); }
        else              { CP_WAIT(0); }
        __syncthreads();
        const float* as = Asb[kt & 1];
        const float* bs = Bsb[kt & 1];
#pragma unroll
        for (int ks = 0; ks < 4; ks++) {
            const int cc = ks * 8 + (lane & 3);
            uint32_t af[2][4];
#pragma unroll
            for (int mf = 0; mf < 2; mf++) {
                int r = wm * 32 + mf * 16 + (lane >> 2);
                af[mf][0] = __float_as_uint(as[cc * MST + r]);
                af[mf][1] = __float_as_uint(as[cc * MST + r + 8]);
                af[mf][2] = __float_as_uint(as[(cc + 4) * MST + r]);
                af[mf][3] = __float_as_uint(as[(cc + 4) * MST + r + 8]);
            }
            uint32_t bf[4][2];
#pragma unroll
            for (int nf = 0; nf < 4; nf++) {
                int rb = wn * 32 + nf * 8 + (lane >> 2);
                bf[nf][0] = __float_as_uint(bs[rb * AST + cc]);
                bf[nf][1] = __float_as_uint(bs[rb * AST + cc + 4]);
            }
#pragma unroll
            for (int mf = 0; mf < 2; mf++)
#pragma unroll
                for (int nf = 0; nf < 4; nf++)
                    mma_tf32(acc[mf][nf][0], acc[mf][nf][1], acc[mf][nf][2], acc[mf][nf][3],
                             af[mf][0], af[mf][1], af[mf][2], af[mf][3],
                             bf[nf][0], bf[nf][1]);
        }
        __syncthreads();
    }

    // epilogue: store + LN partials
    float rs[2][2] = {{0.f,0.f},{0.f,0.f}};
    float rq[2][2] = {{0.f,0.f},{0.f,0.f}};
#pragma unroll
    for (int mf = 0; mf < 2; mf++) {
        int row = m0 + wm * 32 + mf * 16 + (lane >> 2);
#pragma unroll
        for (int nf = 0; nf < 4; nf++) {
            int col = n0 + wn * 32 + nf * 8 + 2 * (lane & 3);
            float bx = bias[col], by = bias[col + 1];
            float2 o0 = make_float2(acc[mf][nf][0] + bx, acc[mf][nf][1] + by);
            float2 o1 = make_float2(acc[mf][nf][2] + bx, acc[mf][nf][3] + by);
            *reinterpret_cast<float2*>(&C[(size_t)row * 192 + col]) = o0;
            *reinterpret_cast<float2*>(&C[(size_t)(row + 8) * 192 + col]) = o1;
            rs[mf][0] += o0.x + o0.y;  rq[mf][0] += o0.x * o0.x + o0.y * o0.y;
            rs[mf][1] += o1.x + o1.y;  rq[mf][1] += o1.x * o1.x + o1.y * o1.y;
        }
    }
#pragma unroll
    for (int mf = 0; mf < 2; mf++)
#pragma unroll
        for (int half = 0; half < 2; half++) {
            float s = rs[mf][half], qq = rq[mf][half];
            s  += __shfl_xor_sync(0xffffffffu, s, 1);
            s  += __shfl_xor_sync(0xffffffffu, s, 2);
            qq += __shfl_xor_sync(0xffffffffu, qq, 1);
            qq += __shfl_xor_sync(0xffffffffu, qq, 2);
            if ((lane & 3) == 0) {
                int row = m0 + wm * 32 + mf * 16 + (lane >> 2) + 8 * half;
                atomicAdd(&g_lns[row], s);
                atomicAdd(&g_lnq[row], qq);
            }
        }
}

// =====================================================================
// qkv GEMM with fused LayerNorm on A (mu/iv computed in-kernel from
// the atomic sums, in-place smem transform). CTA 128x64, warp 32x32.
// Output written as fp16 (half2 pairs).
// =====================================================================
__global__ __launch_bounds__(256, 4)
void k_tcln(const float* __restrict__ A, const float* __restrict__ W,
            const float* __restrict__ bias, __half* __restrict__ Ch, int Ntot,
            const float* __restrict__ cg, const float* __restrict__ cb)
{
    constexpr int K = 192, NCH = 6, AST = 36;
    extern __shared__ float smf[];
    float* Asb[2] = { smf, smf + 128 * AST };
    float* Bsb[2] = { smf + 2 * 128 * AST, smf + 2 * 128 * AST + 64 * AST };
    float* smu = smf + 2 * 128 * AST + 2 * 64 * AST;
    float* siv = smu + 128;

    const int tid  = threadIdx.x;
    const int lane = tid & 31;
    const int warp = tid >> 5;
    const int wm = warp & 3, wn = warp >> 2;
    const int m0 = blockIdx.y * 128;
    const int n0 = blockIdx.x * 64;
    const int arow = tid >> 3, aoff = tid & 7;

    const uint32_t sA[2] = { smem_to_u32(Asb[0]), smem_to_u32(Asb[1]) };
    const uint32_t sB[2] = { smem_to_u32(Bsb[0]), smem_to_u32(Bsb[1]) };

    if (tid < 128) {
        float s = g_lns[m0 + tid], qn = g_lnq[m0 + tid];
        float m = s * (1.0f / 192.0f);
        smu[tid] = m;
        siv[tid] = rsqrtf(qn * (1.0f / 192.0f) - m * m + 1e-5f);
    }

    float acc[2][4][4];
#pragma unroll
    for (int i = 0; i < 2; i++)
#pragma unroll
        for (int j = 0; j < 4; j++)
#pragma unroll
            for (int q = 0; q < 4; q++) acc[i][j][q] = 0.f;

    auto prefetch = [&](int kt) {
        int buf = kt & 1;
        const float* ag = A + (size_t)m0 * K + kt * 32;
        const float* bg = W + (size_t)n0 * K + kt * 32;
#pragma unroll
        for (int j = 0; j < 4; j++) {
            int idx = tid + 256 * j;
            int row = idx >> 3, off = idx & 7;
            CP_ASYNC16(sA[buf] + (uint32_t)(row * AST + off * 4) * 4,
                       ag + (size_t)row * K + off * 4);
        }
#pragma unroll
        for (int j = 0; j < 2; j++) {
            int idx = tid + 256 * j;
            int row = idx >> 3, off = idx & 7;
            CP_ASYNC16(sB[buf] + (uint32_t)(row * AST + off * 4) * 4,
                       bg + (size_t)row * K + off * 4);
        }
        CP_COMMIT();
    };

    prefetch(0);

    for (int kt = 0; kt < NCH; kt++) {
        if (kt + 1 < NCH) { prefetch(kt + 1); CP_WAIT(1); }
        else              { CP_WAIT(0); }
        __syncthreads();
        {   // in-place LayerNorm on A chunk
            float* as = Asb[kt & 1];
            const int k = kt * 32 + aoff * 4;
            float4 g4 = *reinterpret_cast<const float4*>(&cg[k]);
            float4 b4 = *reinterpret_cast<const float4*>(&cb[k]);
#pragma unroll
            for (int j = 0; j < 4; j++) {
                int row = arow + 32 * j;
                float mu = smu[row], iv = siv[row];
                float4 v = *reinterpret_cast<float4*>(&as[row * AST + aoff * 4]);
                v.x = (v.x - mu) * iv * g4.x + b4.x;
                v.y = (v.y - mu) * iv * g4.y + b4.y;
                v.z = (v.z - mu) * iv * g4.z + b4.z;
                v.w = (v.w - mu) * iv * g4.w + b4.w;
                *reinterpret_cast<float4*>(&as[row * AST + aoff * 4]) = v;
            }
        }
        __syncthreads();
        const float* as = Asb[kt & 1];
        const float* bs = Bsb[kt & 1];
#pragma unroll
        for (int ks = 0; ks < 4; ks++) {
            const int cc = ks * 8 + (lane & 3);
            uint32_t af[2][4];
#pragma unroll
            for (int mf = 0; mf < 2; mf++) {
                int r = wm * 32 + mf * 16 + (lane >> 2);
                af[mf][0] = __float_as_uint(as[r * AST + cc]);
                af[mf][1] = __float_as_uint(as[(r + 8) * AST + cc]);
                af[mf][2] = __float_as_uint(as[r * AST + cc + 4]);
                af[mf][3] = __float_as_uint(as[(r + 8) * AST + cc + 4]);
            }
            uint32_t bf[4][2];
#pragma unroll
            for (int nf = 0; nf < 4; nf++) {
                int rb = wn * 32 + nf * 8 + (lane >> 2);
                bf[nf][0] = __float_as_uint(bs[rb * AST + cc]);
                bf[nf][1] = __float_as_uint(bs[rb * AST + cc + 4]);
            }
#pragma unroll
            for (int mf = 0; mf < 2; mf++)
#pragma unroll
                for (int nf = 0; nf < 4; nf++)
                    mma_tf32(acc[mf][nf][0], acc[mf][nf][1], acc[mf][nf][2], acc[mf][nf][3],
                             af[mf][0], af[mf][1], af[mf][2], af[mf][3],
                             bf[nf][0], bf[nf][1]);
        }
        __syncthreads();
    }

#pragma unroll
    for (int mf = 0; mf < 2; mf++) {
        int row = m0 + wm * 32 + mf * 16 + (lane >> 2);
#pragma unroll
        for (int nf = 0; nf < 4; nf++) {
            int col = n0 + wn * 32 + nf * 8 + 2 * (lane & 3);
            float bx = bias[col], by = bias[col + 1];
            __half2 h0 = __floats2half2_rn(acc[mf][nf][0] + bx, acc[mf][nf][1] + by);
            __half2 h1 = __floats2half2_rn(acc[mf][nf][2] + bx, acc[mf][nf][3] + by);
            *reinterpret_cast<__half2*>(&Ch[(size_t)row * Ntot + col]) = h0;
            *reinterpret_cast<__half2*>(&Ch[(size_t)(row + 8) * Ntot + col]) = h1;
        }
    }
}

// =====================================================================
// out_proj GEMM + fused GN1 partial stats. CTA 128x64, warp 32x32.
// =====================================================================
__global__ __launch_bounds__(256, 4)
void k_tc2(const float* __restrict__ A, const float* __restrict__ W,
           const float* __restrict__ bias, float* __restrict__ C)
{
    constexpr int K = 192, NCH = 6, AST = 36;
    extern __shared__ float smf[];
    float* Asb[2] = { smf, smf + 128 * AST };
    float* Bsb[2] = { smf + 2 * 128 * AST, smf + 2 * 128 * AST + 64 * AST };

    const int tid  = threadIdx.x;
    const int lane = tid & 31;
    const int warp = tid >> 5;
    const int wm = warp & 3, wn = warp >> 2;
    const int m0 = blockIdx.y * 128;
    const int n0 = blockIdx.x * 64;

    const uint32_t sA[2] = { smem_to_u32(Asb[0]), smem_to_u32(Asb[1]) };
    const uint32_t sB[2] = { smem_to_u32(Bsb[0]), smem_to_u32(Bsb[1]) };

    float acc[2][4][4];
#pragma unroll
    for (int i = 0; i < 2; i++)
#pragma unroll
        for (int j = 0; j < 4; j++)
#pragma unroll
            for (int q = 0; q < 4; q++) acc[i][j][q] = 0.f;

    auto prefetch = [&](int kt) {
        int buf = kt & 1;
        const float* ag = A + (size_t)m0 * K + kt * 32;
        const float* bg = W + (size_t)n0 * K + kt * 32;
#pragma unroll
        for (int j = 0; j < 4; j++) {
            int idx = tid + 256 * j;
            int row = idx >> 3, off = idx & 7;
            CP_ASYNC16(sA[buf] + (uint32_t)(row * AST + off * 4) * 4,
                       ag + (size_t)row * K + off * 4);
        }
#pragma unroll
        for (int j = 0; j < 2; j++) {
            int idx = tid + 256 * j;
            int row = idx >> 3, off = idx & 7;
            CP_ASYNC16(sB[buf] + (uint32_t)(row * AST + off * 4) * 4,
                       bg + (size_t)row * K + off * 4);
        }
        CP_COMMIT();
    };

    prefetch(0);

    for (int kt = 0; kt < NCH; kt++) {
        if (kt + 1 < NCH) { prefetch(kt + 1); CP_WAIT(1); }
        else              { CP_WAIT(0); }
        __syncthreads();
        const float* as = Asb[kt & 1];
        const float* bs = Bsb[kt & 1];
#pragma unroll
        for (int ks = 0; ks < 4; ks++) {
            const int cc = ks * 8 + (lane & 3);
            uint32_t af[2][4];
#pragma unroll
            for (int mf = 0; mf < 2; mf++) {
                int r = wm * 32 + mf * 16 + (lane >> 2);
                af[mf][0] = __float_as_uint(as[r * AST + cc]);
                af[mf][1] = __float_as_uint(as[(r + 8) * AST + cc]);
                af[mf][2] = __float_as_uint(as[r * AST + cc + 4]);
                af[mf][3] = __float_as_uint(as[(r + 8) * AST + cc + 4]);
            }
            uint32_t bf[4][2];
#pragma unroll
            for (int nf = 0; nf < 4; nf++) {
                int rb = wn * 32 + nf * 8 + (lane >> 2);
                bf[nf][0] = __float_as_uint(bs[rb * AST + cc]);
                bf[nf][1] = __float_as_uint(bs[rb * AST + cc + 4]);
            }
#pragma unroll
            for (int mf = 0; mf < 2; mf++)
#pragma unroll
                for (int nf = 0; nf < 4; nf++)
                    mma_tf32(acc[mf][nf][0], acc[mf][nf][1], acc[mf][nf][2], acc[mf][nf][3],
                             af[mf][0], af[mf][1], af[mf][2], af[mf][3],
                             bf[nf][0], bf[nf][1]);
        }
        __syncthreads();
    }

    const int bb = m0 >> 14;
#pragma unroll
    for (int nf = 0; nf < 4; nf++) {
        float s = 0.f, qq = 0.f;
        int col = n0 + wn * 32 + nf * 8 + 2 * (lane & 3);
        float bx = bias[col], by = bias[col + 1];
#pragma unroll
        for (int mf = 0; mf < 2; mf++) {
            int row = m0 + wm * 32 + mf * 16 + (lane >> 2);
            float2 o0 = make_float2(acc[mf][nf][0] + bx, acc[mf][nf][1] + by);
            float2 o1 = make_float2(acc[mf][nf][2] + bx, acc[mf][nf][3] + by);
            *reinterpret_cast<float2*>(&C[(size_t)row * 192 + col]) = o0;
            *reinterpret_cast<float2*>(&C[(size_t)(row + 8) * 192 + col]) = o1;
            s  += o0.x + o0.y + o1.x + o1.y;
            qq += o0.x * o0.x + o0.y * o0.y + o1.x * o1.x + o1.y * o1.y;
        }
#pragma unroll
        for (int o = 16; o; o >>= 1) {
            s  += __shfl_xor_sync(0xffffffffu, s, o);
            qq += __shfl_xor_sync(0xffffffffu, qq, o);
        }
        if (lane == 0) {
            int g = (n0 + wn * 32 + nf * 8) / 24;
            atomicAdd(&g_g1s[bb * 8 + g], s);
            atomicAdd(&g_g1q[bb * 8 + g], qq);
        }
    }
}

// =====================================================================
// gates GEMM (permuted W) + register-space GN on A (S/T fold, GN1
// finalize done in-kernel) + LSTM epilogue + GN2 partial stats.
// =====================================================================
__global__ __launch_bounds__(256, 4)
void k_tcg(const float* __restrict__ A, const float* __restrict__ W,
           const float* __restrict__ bias,
           const float* __restrict__ cg, const float* __restrict__ cb,
           const float* __restrict__ Cin, float* __restrict__ out)
{
    constexpr int K = 192, NCH = 6, AST = 36;
    extern __shared__ float smf[];
    float* Asb[2] = { smf, smf + 128 * AST };
    float* Bsb[2] = { smf + 2 * 128 * AST, smf + 2 * 128 * AST + 64 * AST };
    float* sS = smf + 2 * 128 * AST + 2 * 64 * AST;
    float* sT = sS + 192;

    const int tid  = threadIdx.x;
    const int lane = tid & 31;
    const int warp = tid >> 5;
    const int wm = warp & 3, wn = warp >> 2;
    const int m0 = blockIdx.y * 128;
    const int n0 = blockIdx.x * 64;
    const int b8 = (m0 >> 14) << 3;

    const uint32_t sA[2] = { smem_to_u32(Asb[0]), smem_to_u32(Asb[1]) };
    const uint32_t sB[2] = { smem_to_u32(Bsb[0]), smem_to_u32(Bsb[1]) };

    if (tid < 192) {     // fold GN1 finalize: S[k], T[k]
        int grp = tid / 24;
        const float inv_n = 1.0f / 393216.0f;
        float m = g_g1s[b8 + grp] * inv_n;
        float iv = rsqrtf(g_g1q[b8 + grp] * inv_n - m * m + 1e-5f);
        float gv = cg[tid];
        sS[tid] = iv * gv;
        sT[tid] = cb[tid] - m * iv * gv;
    }

    float acc[2][4][4];
#pragma unroll
    for (int i = 0; i < 2; i++)
#pragma unroll
        for (int j = 0; j < 4; j++)
#pragma unroll
            for (int q = 0; q < 4; q++) acc[i][j][q] = 0.f;

    auto prefetch = [&](int kt) {
        int buf = kt & 1;
        const float* ag = A + (size_t)m0 * K + kt * 32;
        const float* bg = W + (size_t)n0 * K + kt * 32;
#pragma unroll
        for (int j = 0; j < 4; j++) {
            int idx = tid + 256 * j;
            int row = idx >> 3, off = idx & 7;
            CP_ASYNC16(sA[buf] + (uint32_t)(row * AST + off * 4) * 4,
                       ag + (size_t)row * K + off * 4);
        }
#pragma unroll
        for (int j = 0; j < 2; j++) {
            int idx = tid + 256 * j;
            int row = idx >> 3, off = idx & 7;
            CP_ASYNC16(sB[buf] + (uint32_t)(row * AST + off * 4) * 4,
                       bg + (size_t)row * K + off * 4);
        }
        CP_COMMIT();
    };

    prefetch(0);

    for (int kt = 0; kt < NCH; kt++) {
        if (kt + 1 < NCH) { prefetch(kt + 1); CP_WAIT(1); }
        else              { CP_WAIT(0); }
        __syncthreads();
        const float* as = Asb[kt & 1];
        const float* bs = Bsb[kt & 1];
#pragma unroll
        for (int ks = 0; ks < 4; ks++) {
            const int cc = ks * 8 + (lane & 3);
            const int kg = kt * 32 + cc;
            float S0 = sS[kg], T0 = sT[kg];
            float S1 = sS[kg + 4], T1 = sT[kg + 4];
            uint32_t af[2][4];
#pragma unroll
            for (int mf = 0; mf < 2; mf++) {
                int r = wm * 32 + mf * 16 + (lane >> 2);
                af[mf][0] = __float_as_uint(fmaf(as[r * AST + cc],       S0, T0));
                af[mf][1] = __float_as_uint(fmaf(as[(r + 8) * AST + cc], S0, T0));
                af[mf][2] = __float_as_uint(fmaf(as[r * AST + cc + 4],   S1, T1));
                af[mf][3] = __float_as_uint(fmaf(as[(r + 8) * AST + cc + 4], S1, T1));
            }
            uint32_t bf[4][2];
#pragma unroll
            for (int nf = 0; nf < 4; nf++) {
                int rb = wn * 32 + nf * 8 + (lane >> 2);
                bf[nf][0] = __float_as_uint(bs[rb * AST + cc]);
                bf[nf][1] = __float_as_uint(bs[rb * AST + cc + 4]);
            }
#pragma unroll
            for (int mf = 0; mf < 2; mf++)
#pragma unroll
                for (int nf = 0; nf < 4; nf++)
                    mma_tf32(acc[mf][nf][0], acc[mf][nf][1], acc[mf][nf][2], acc[mf][nf][3],
                             af[mf][0], af[mf][1], af[mf][2], af[mf][3],
                             bf[nf][0], bf[nf][1]);
        }
        __syncthreads();
    }

    // ---- LSTM epilogue + GN2 partials ----
    const int q = lane & 3;
    const int t = blockIdx.x;
    const int chA = t * 16 + wn * 8 + q;
    const int chB = chA + 4;
    const int colb = n0 + wn * 32 + 2 * q;
    float bIA = bias[colb + 0],  bFA = bias[colb + 1];
    float bOA = bias[colb + 8],  bGA = bias[colb + 9];
    float bIB = bias[colb + 16], bFB = bias[colb + 17];
    float bOB = bias[colb + 24], bGB = bias[colb + 25];

    const int bt = m0 >> 14;
    const size_t baseA = ((size_t)(bt * 192 + chA)) << 14;
    const size_t baseB = ((size_t)(bt * 192 + chB)) << 14;

    float sA_ = 0.f, qA_ = 0.f, sB_ = 0.f, qB_ = 0.f;
#pragma unroll
    for (int mf = 0; mf < 2; mf++) {
        int p = (m0 + wm * 32 + mf * 16 + (lane >> 2)) & 16383;
#pragma unroll
        for (int half = 0; half < 2; half++) {
            int pp = p + half * 8;
            int a0 = half * 2;
            {
                float gi = acc[mf][0][a0]     + bIA;
                float gf = acc[mf][0][a0 + 1] + bFA;
                float go = acc[mf][1][a0]     + bOA;
                float gg = acc[mf][1][a0 + 1] + bGA;
                float i_ = 1.f / (1.f + __expf(-gi));
                float f_ = 1.f / (1.f + __expf(-gf));
                float o_ = 1.f / (1.f + __expf(-go));
                float g_ = tanhf(gg);
                size_t addr = baseA + pp;
                float cn = f_ * Cin[addr] + i_ * g_;
                out[(size_t)HSZ + addr] = cn;
                float hv = o_ * tanhf(cn);
                g_hraw[addr] = hv;
                sA_ += hv; qA_ += hv * hv;
            }
            {
                float gi = acc[mf][2][a0]     + bIB;
                float gf = acc[mf][2][a0 + 1] + bFB;
                float go = acc[mf][3][a0]     + bOB;
                float gg = acc[mf][3][a0 + 1] + bGB;
                float i_ = 1.f / (1.f + __expf(-gi));
                float f_ = 1.f / (1.f + __expf(-gf));
                float o_ = 1.f / (1.f + __expf(-go));
                float g_ = tanhf(gg);
                size_t addr = baseB + pp;
                float cn = f_ * Cin[addr] + i_ * g_;
                out[(size_t)HSZ + addr] = cn;
                float hv = o_ * tanhf(cn);
                g_hraw[addr] = hv;
                sB_ += hv; qB_ += hv * hv;
            }
        }
    }
#pragma unroll
    for (int o = 16; o; o >>= 1) {
        sA_ += __shfl_xor_sync(0xffffffffu, sA_, o);
        qA_ += __shfl_xor_sync(0xffffffffu, qA_, o);
        sB_ += __shfl_xor_sync(0xffffffffu, sB_, o);
        qB_ += __shfl_xor_sync(0xffffffffu, qB_, o);
    }
    if (lane == 0) {
        int gA = (t * 16 + wn * 8) / 24;
        int gB = (t * 16 + wn * 8 + 4) / 24;
        atomicAdd(&g_g2s[bt * 8 + gA], sA_);
        atomicAdd(&g_g2q[bt * 8 + gA], qA_);
        atomicAdd(&g_g2s[bt * 8 + gB], sB_);
        atomicAdd(&g_g2q[bt * 8 + gB], qB_);
    }
}

// =====================================================================
// Window attention — fp16 qkv in smem, fp32 compute.
// 4 windows/CTA, cp.async double-buffered, quad-shfl softmax.
// =====================================================================
#define QSH 584            // halves per row (576 data + 8 pad)
__global__ __launch_bounds__(256, 2)
void k_attn()
{
    extern __shared__ char smc[];
    __half* sq0 = reinterpret_cast<__half*>(smc);
    __half* sq1 = sq0 + 16 * QSH;
    float*  ss  = reinterpret_cast<float*>(smc + 2 * 16 * QSH * 2);   // 1024 floats

    const int tid = threadIdx.x;

    auto prefetch = [&](int w, __half* buf) {
        int b = w >> 10, wi = w & 1023, wy = wi >> 5, wx = wi & 31;
        int rowbase = (b << 14) + (wy << 9) + (wx << 2);
        uint32_t sbase = smem_to_u32(buf);
        // 16 rows x 72 chunks of 8 halves (16B) = 1152 chunks
#pragma unroll
        for (int j = 0; j < 5; j++) {
            int i = tid + 256 * j;
            if (i < 1152) {
                int t = i / 72, c8 = i - t * 72;
                int tok = rowbase + ((t >> 2) << 7) + (t & 3);
                CP_ASYNC16(sbase + (uint32_t)(t * QSH + c8 * 8) * 2,
                           &g_qkvh[(size_t)tok * 576 + c8 * 8]);
            }
        }
        CP_COMMIT();
    };

    const int w0 = blockIdx.x * 4;
    prefetch(w0, sq0);

    for (int it = 0; it < 4; it++) {
        if (it < 3) { prefetch(w0 + it + 1, (it & 1) ? sq0 : sq1); CP_WAIT(1); }
        else        { CP_WAIT(0); }
        __syncthreads();
        const __half* sqb = (it & 1) ? sq1 : sq0;
        int w = w0 + it;
        int b = w >> 10, wi = w & 1023, wy = wi >> 5, wx = wi & 31;
        int rowbase = (b << 14) + (wy << 9) + (wx << 2);

        {   // scores + quad-shfl softmax (row (h,r) spans lanes cl=0..3)
            int h = tid >> 6, r = (tid >> 2) & 15, cl = tid & 3;
            const __half* qrow = sqb + r * QSH + h * 48;
            float qvf[48];
#pragma unroll
            for (int k8 = 0; k8 < 6; k8++) {
                uint4 u = *reinterpret_cast<const uint4*>(qrow + k8 * 8);
                h8_to_f8(u, &qvf[k8 * 8]);
            }
            float d[4];
#pragma unroll
            for (int cc = 0; cc < 4; cc++) {
                int col = cl + 4 * cc;
                const __half* krow = sqb + col * QSH + 192 + h * 48;
                float dd = 0.f;
#pragma unroll
                for (int k8 = 0; k8 < 6; k8++) {
                    uint4 u = *reinterpret_cast<const uint4*>(krow + k8 * 8);
                    float kf[8];
                    h8_to_f8(u, kf);
#pragma unroll
                    for (int e = 0; e < 8; e++) dd += qvf[k8 * 8 + e] * kf[e];
                }
                d[cc] = dd * 0.14433756729740643f;
            }
            float mx = fmaxf(fmaxf(d[0], d[1]), fmaxf(d[2], d[3]));
            mx = fmaxf(mx, __shfl_xor_sync(0xffffffffu, mx, 1));
            mx = fmaxf(mx, __shfl_xor_sync(0xffffffffu, mx, 2));
            float e4[4], sm = 0.f;
#pragma unroll
            for (int cc = 0; cc < 4; cc++) { e4[cc] = __expf(d[cc] - mx); sm += e4[cc]; }
            sm += __shfl_xor_sync(0xffffffffu, sm, 1);
            sm += __shfl_xor_sync(0xffffffffu, sm, 2);
            float rinv = 1.f / sm;
#pragma unroll
            for (int cc = 0; cc < 4; cc++)
                ss[(h * 16 + r) * 16 + cl + 4 * cc] = e4[cc] * rinv;
        }
        __syncthreads();

        if (tid < 192) {      // AV: V 4-half loads reused across 4 rows
            int c4 = tid % 48;
            int rp = tid / 48;
            int h = c4 / 12;
            const __half* vbase = sqb + 384 + c4 * 4;
            float4 o[4];
#pragma unroll
            for (int rr = 0; rr < 4; rr++) o[rr] = make_float4(0.f, 0.f, 0.f, 0.f);
#pragma unroll
            for (int jj = 0; jj < 16; jj++) {
                uint2 vu = *reinterpret_cast<const uint2*>(vbase + jj * QSH);
                float2 v01 = __half22float2(*reinterpret_cast<__half2*>(&vu.x));
                float2 v23 = __half22float2(*reinterpret_cast<__half2*>(&vu.y));
#pragma unroll
                for (int rr = 0; rr < 4; rr++) {
                    float sv = ss[(h * 16 + rp + rr * 4) * 16 + jj];
                    o[rr].x += sv * v01.x; o[rr].y += sv * v01.y;
                    o[rr].z += sv * v23.x; o[rr].w += sv * v23.y;
                }
            }
#pragma unroll
            for (int rr = 0; rr < 4; rr++) {
                int tok = rowbase + (rr << 7) + rp;
                *reinterpret_cast<float4*>(&g_attn[(size_t)tok * 192 + c4 * 4]) = o[rr];
            }
        }
        __syncthreads();      // protect ss + buffer for next iteration
    }
}

// =====================================================================
// final GN apply on hraw (GN2 finalize folded in) — 4 float4/thread
// =====================================================================
__global__ __launch_bounds__(256)
void k_finalize(const float* __restrict__ gg, const float* __restrict__ gb,
                float* __restrict__ out)
{
    __shared__ float sp[2];
    size_t base0 = (size_t)blockIdx.x * 4096;
    if (threadIdx.x == 0) {
        int bc = (int)(base0 >> 14);
        int b = bc / 192, cch = bc - b * 192;
        int grp = cch / 24;
        const float inv_n = 1.0f / 393216.0f;
        float m = g_g2s[b * 8 + grp] * inv_n;
        float iv = rsqrtf(g_g2q[b * 8 + grp] * inv_n - m * m + 1e-5f);
        float sc = gg[cch] * iv;
        sp[0] = sc;
        sp[1] = gb[cch] - m * sc;
    }
    __syncthreads();
    float sc = sp[0], bi = sp[1];
    size_t base = base0 + (size_t)threadIdx.x * 4;
    float4 v0 = *reinterpret_cast<const float4*>(&g_hraw[base]);
    float4 v1 = *reinterpret_cast<const float4*>(&g_hraw[base + 1024]);
    float4 v2 = *reinterpret_cast<const float4*>(&g_hraw[base + 2048]);
    float4 v3 = *reinterpret_cast<const float4*>(&g_hraw[base + 3072]);
    float4 o0, o1, o2, o3;
    o0.x = v0.x * sc + bi; o0.y = v0.y * sc + bi; o0.z = v0.z * sc + bi; o0.w = v0.w * sc + bi;
    o1.x = v1.x * sc + bi; o1.y = v1.y * sc + bi; o1.z = v1.z * sc + bi; o1.w = v1.w * sc + bi;
    o2.x = v2.x * sc + bi; o2.y = v2.y * sc + bi; o2.z = v2.z * sc + bi; o2.w = v2.w * sc + bi;
    o3.x = v3.x * sc + bi; o3.y = v3.y * sc + bi; o3.z = v3.z * sc + bi; o3.w = v3.w * sc + bi;
    *reinterpret_cast<float4*>(&out[base])        = o0;
    *reinterpret_cast<float4*>(&out[base + 1024]) = o1;
    *reinterpret_cast<float4*>(&out[base + 2048]) = o2;
    *reinterpret_cast<float4*>(&out[base + 3072]) = o3;
}

// =====================================================================
// host launcher
// =====================================================================
extern "C" void kernel_launch(void* const* d_in, const int* in_sizes, int n_in,
                              void* d_out, int out_size)
{
    const float* x       = (const float*)d_in[0];
    const float* h       = (const float*)d_in[1];
    const float* c       = (const float*)d_in[2];
    const float* w_in    = (const float*)d_in[3];
    const float* b_in    = (const float*)d_in[4];
    const float* ln_g    = (const float*)d_in[5];
    const float* ln_b    = (const float*)d_in[6];
    const float* w_qkv   = (const float*)d_in[7];
    const float* b_qkv   = (const float*)d_in[8];
    const float* w_proj  = (const float*)d_in[9];
    const float* b_proj  = (const float*)d_in[10];
    const float* gn_g    = (const float*)d_in[11];
    const float* gn_b    = (const float*)d_in[12];
    const float* w_gates = (const float*)d_in[13];
    const float* b_gates = (const float*)d_in[14];
    float* out = (float*)d_out;

    void *p_proj, *p_qkvh, *p_attn, *p_amap, *p_wperm, *p_bperm;
    cudaGetSymbolAddress(&p_proj,  g_proj);
    cudaGetSymbolAddress(&p_qkvh,  g_qkvh);
    cudaGetSymbolAddress(&p_attn,  g_attn);
    cudaGetSymbolAddress(&p_amap,  g_amap);
    cudaGetSymbolAddress(&p_wperm, g_wperm);
    cudaGetSymbolAddress(&p_bperm, g_bperm);

    const int SM_TC = (2 * 128 + 2 * 64) * 36 * 4;                 // 55296
    const int SM_LN = SM_TC + 256 * 4;                             // 56320
    const int SM_GT = SM_TC + 384 * 4;                             // 56832
    const int SM_IN = (2 * 32 * 136 + 2 * 64 * 36) * 4;            // 53248
    const int SM_AT = 2 * 16 * QSH * 2 + 1024 * 4;                 // 41472
    cudaFuncSetAttribute(k_tcln, cudaFuncAttributeMaxDynamicSharedMemorySize, SM_LN);
    cudaFuncSetAttribute(k_tc2,  cudaFuncAttributeMaxDynamicSharedMemorySize, SM_TC);
    cudaFuncSetAttribute(k_tcg,  cudaFuncAttributeMaxDynamicSharedMemorySize, SM_GT);
    cudaFuncSetAttribute(k_tc_in, cudaFuncAttributeMaxDynamicSharedMemorySize, SM_IN);
    cudaFuncSetAttribute(k_attn, cudaFuncAttributeMaxDynamicSharedMemorySize, SM_AT);

    // 0) prep: permute gates weights + zero stat accumulators
    k_prep<<<768, 192>>>(w_gates, b_gates);
    // 1) in_proj GEMM (gather) + LN partial stats
    k_tc_in<<<dim3(3, 1024), 256, SM_IN>>>(x, h, w_in, b_in, (float*)p_proj);
    // 2) qkv GEMM with fused LayerNorm -> fp16 qkv
    k_tcln<<<dim3(9, 1024), 256, SM_LN>>>((const float*)p_proj, w_qkv, b_qkv,
                                          (__half*)p_qkvh, 576, ln_g, ln_b);
    // 3) window attention (fp16 qkv, fp32 compute)
    k_attn<<<2048, 256, SM_AT>>>();
    // 4) out_proj GEMM + GN1 partial stats
    k_tc2<<<dim3(3, 1024), 256, SM_TC>>>((const float*)p_attn, w_proj, b_proj,
                                         (float*)p_amap);
    // 5) gates GEMM + GN on A (gn1 finalize folded) + LSTM + GN2 partials
    k_tcg<<<dim3(12, 1024), 256, SM_GT>>>((const float*)p_amap, (const float*)p_wperm,
                                          (const float*)p_bperm,
                                          gn_g, gn_b, c, out);
    // 6) GN2 finalize + apply -> d_out first half
    k_finalize<<<6144, 256>>>(gn_g, gn_b, out);
}